// round 10
// baseline (speedup 1.0000x reference)
#include <cuda_runtime.h>
#include <cuda_bf16.h>
#include <cuda_fp16.h>
#include <math.h>

// Problem constants
#define BATCH 8
#define NTOK 1024
#define DIMC 512
#define NH 16
#define HD 32
#define TABLE_SZ 3969
#define SEQ_SCALE 6.93147180559945309f  // ln(1024)
#define MFIX 33.0f                      // fixed softmax shift (|logit| <= ~33)

// ---------------- scratch (device globals; no allocation allowed) -------------
__device__ float g_scale[NH];
__device__ float g_t[TABLE_SZ * NH];
__device__ __half g_biash[NH * NTOK * NTOK];            // [h][n][m] 32MB fp16
__device__ float g_qkv[BATCH * NTOK * 3 * DIMC];        // 50MB
__device__ unsigned g_qh[BATCH * NH * NTOK * HD / 2];   // q hi, packed bf16 pairs
__device__ unsigned g_ql[BATCH * NH * NTOK * HD / 2];   // q lo
__device__ unsigned g_kh[BATCH * NH * NTOK * HD / 2];   // k hi
__device__ unsigned g_kl[BATCH * NH * NTOK * HD / 2];   // k lo
__device__ unsigned g_vt[BATCH * NH * NTOK * HD];       // v tf32
__device__ unsigned g_oh[BATCH * NTOK * DIMC / 2];      // attn out hi (bf16 pairs)
__device__ unsigned g_ol[BATCH * NTOK * DIMC / 2];      // attn out lo
__device__ unsigned g_xh[BATCH * NTOK * DIMC / 2];      // x hi
__device__ unsigned g_xl[BATCH * NTOK * DIMC / 2];      // x lo
__device__ unsigned g_wh[(3 * DIMC + DIMC) * DIMC / 2]; // W hi (qkv then proj)
__device__ unsigned g_wl[(3 * DIMC + DIMC) * DIMC / 2]; // W lo

// ---------------- helpers -----------------------------------------------------
__device__ __forceinline__ unsigned tf32_rna(float x) {
    unsigned r; asm("cvt.rna.tf32.f32 %0, %1;" : "=r"(r) : "f"(x)); return r;
}
__device__ __forceinline__ void bf16_split2(float e, float o, unsigned& hi, unsigned& lo) {
    __nv_bfloat162 h2 = __floats2bfloat162_rn(e, o);
    hi = *(unsigned*)&h2;
    float re = e - __bfloat162float(h2.x);
    float ro = o - __bfloat162float(h2.y);
    __nv_bfloat162 l2 = __floats2bfloat162_rn(re, ro);
    lo = *(unsigned*)&l2;
}
__device__ __forceinline__ void mma16(float* c, const unsigned* a, const unsigned* b) {
    asm volatile("mma.sync.aligned.m16n8k16.row.col.f32.bf16.bf16.f32 "
                 "{%0,%1,%2,%3}, {%4,%5,%6,%7}, {%8,%9}, {%0,%1,%2,%3};"
                 : "+f"(c[0]), "+f"(c[1]), "+f"(c[2]), "+f"(c[3])
                 : "r"(a[0]), "r"(a[1]), "r"(a[2]), "r"(a[3]),
                   "r"(b[0]), "r"(b[1]));
}
__device__ __forceinline__ void mma8t(float* c, const unsigned* a, const unsigned* b) {
    asm volatile("mma.sync.aligned.m16n8k8.row.col.f32.tf32.tf32.f32 "
                 "{%0,%1,%2,%3}, {%4,%5,%6,%7}, {%8,%9}, {%0,%1,%2,%3};"
                 : "+f"(c[0]), "+f"(c[1]), "+f"(c[2]), "+f"(c[3])
                 : "r"(a[0]), "r"(a[1]), "r"(a[2]), "r"(a[3]),
                   "r"(b[0]), "r"(b[1]));
}
__device__ __forceinline__ void ldsm4(unsigned& r0, unsigned& r1, unsigned& r2,
                                      unsigned& r3, const void* p) {
    unsigned a = (unsigned)__cvta_generic_to_shared(p);
    asm volatile("ldmatrix.sync.aligned.m8n8.x4.shared.b16 {%0,%1,%2,%3}, [%4];"
                 : "=r"(r0), "=r"(r1), "=r"(r2), "=r"(r3) : "r"(a));
}
__device__ __forceinline__ void cp16(void* sdst, const void* gsrc) {
    unsigned u = (unsigned)__cvta_generic_to_shared(sdst);
    asm volatile("cp.async.ca.shared.global [%0], [%1], 16;" :: "r"(u), "l"(gsrc));
}
#define CP_COMMIT() asm volatile("cp.async.commit_group;")
#define CP_WAIT(n)  asm volatile("cp.async.wait_group %0;" :: "n"(n))

// swizzled u32 offset for (row, 16B-chunk) in a 128x16-u32 tile (64B rows)
#define SWZ(row, chunk) (((row) * 16) + ((((chunk) ^ ((row) >> 1)) & 3) * 4))

// ---------------- fused split: weights + x (bf16 hi/lo pairs) ------------------
#define NW2 (4 * DIMC * DIMC / 2)
#define NX2 (BATCH * NTOK * DIMC / 2)
__global__ void split_kernel(const float* __restrict__ qkvw,
                             const float* __restrict__ projw,
                             const float* __restrict__ x) {
    int i = blockIdx.x * 256 + threadIdx.x;
    unsigned h, l;
    if (i < NW2) {
        int nq2 = 3 * DIMC * DIMC / 2;
        float2 v = (i < nq2) ? ((const float2*)qkvw)[i] : ((const float2*)projw)[i - nq2];
        bf16_split2(v.x, v.y, h, l);
        g_wh[i] = h; g_wl[i] = l;
    } else {
        int j = i - NW2;
        float2 v = ((const float2*)x)[j];
        bf16_split2(v.x, v.y, h, l);
        g_xh[j] = h; g_xl[j] = l;
    }
}

// ---------------- CPB MLP t[r][h] (+ fused temperature scale) -----------------
__global__ void cpb_kernel(const float* __restrict__ table,
                           const float* __restrict__ fc1w,
                           const float* __restrict__ fc1b,
                           const float* __restrict__ fc2w,
                           const float* __restrict__ fc2b,
                           const float* __restrict__ temp) {
    __shared__ float hid[512];
    int r = blockIdx.x;
    int j = threadIdx.x;
    if (r == 0 && j < NH) {
        float t = temp[j];
        float sp = (t > 20.0f) ? t : log1pf(expf(t));
        g_scale[j] = sp * SEQ_SCALE;
    }
    float c0 = table[r * 2 + 0];
    float c1 = table[r * 2 + 1];
    float hv = c0 * fc1w[j * 2 + 0] + c1 * fc1w[j * 2 + 1] + fc1b[j];
    hid[j] = fmaxf(hv, 0.0f);
    __syncthreads();
    int w = j >> 5;
    int lane = j & 31;
    float acc = 0.0f;
#pragma unroll
    for (int kk = lane; kk < 512; kk += 32) acc += hid[kk] * fc2w[w * 512 + kk];
#pragma unroll
    for (int off = 16; off >= 1; off >>= 1) acc += __shfl_xor_sync(0xffffffffu, acc, off);
    if (lane == 0) g_t[r * NH + w] = acc + fc2b[w];
}

// ---------------- bias gather  biash[h][n][m] = half(t[rpi[n][m]][h]) ---------
__global__ void bias_kernel(const int* __restrict__ rpi) {
    int n = blockIdx.x;
    for (int m = threadIdx.x; m < NTOK; m += blockDim.x) {
        int idx = rpi[n * NTOK + m];
        const float4* tp = (const float4*)(g_t + idx * NH);
        float4 t0 = tp[0], t1 = tp[1], t2 = tp[2], t3 = tp[3];
        float v[16] = {t0.x, t0.y, t0.z, t0.w, t1.x, t1.y, t1.z, t1.w,
                       t2.x, t2.y, t2.z, t2.w, t3.x, t3.y, t3.z, t3.w};
#pragma unroll
        for (int h = 0; h < NH; h++)
            g_biash[((size_t)h * NTOK + n) * NTOK + m] = __float2half(v[h]);
    }
}

// ---------------- 3xBF16 GEMM: swizzled smem, 3-stage cp.async, 1 sync/iter ----
// BM=BN=128, BK=32 floats (16 u32). Stage = 4 arrays x 2048 u32 = 32KB; 3 stages.
#define GEMM_SMEM (3 * 4 * 2048 * 4)
__global__ __launch_bounds__(256, 2) void gemm3b(const unsigned* __restrict__ Ah,
                                                 const unsigned* __restrict__ Al,
                                                 const unsigned* __restrict__ Wh,
                                                 const unsigned* __restrict__ Wl,
                                                 const float* __restrict__ bias,
                                                 float* __restrict__ C,
                                                 int M, int Nn, int K) {
    extern __shared__ unsigned smg[];
    unsigned* Ahs = smg;               // [3][2048]
    unsigned* Als = smg + 3 * 2048;
    unsigned* Whs = smg + 6 * 2048;
    unsigned* Wls = smg + 9 * 2048;

    int tid = threadIdx.x;
    int wid = tid >> 5, lane = tid & 31;
    int g = lane >> 2, tg = lane & 3;
    int wm = wid & 3, wn = wid >> 2;
    int m0 = blockIdx.y * 128, n0 = blockIdx.x * 128;
    int KU = K >> 1;

    int lrow = tid >> 2, lc = tid & 3;          // loader: row 0..63 (+64), chunk 0..3
    int a_r = (lane & 15), a_ch = (lane >> 4);            // A ldmatrix: row off, chunk off
    int b_r = (lane >> 4) * 8 + (lane & 7), b_ch = ((lane >> 3) & 1);

    float acc[2][8][4];
#pragma unroll
    for (int mi = 0; mi < 2; mi++)
#pragma unroll
        for (int j = 0; j < 8; j++)
#pragma unroll
            for (int c = 0; c < 4; c++) acc[mi][j][c] = 0.0f;

    int nk = K >> 5;
#define G_LOAD(stage, ku0)                                                        \
    do {                                                                          \
        cp16(&Ahs[(stage) * 2048 + SWZ(lrow, lc)], Ah + (size_t)(m0 + lrow) * KU + (ku0) + lc * 4);           \
        cp16(&Ahs[(stage) * 2048 + SWZ(lrow + 64, lc)], Ah + (size_t)(m0 + lrow + 64) * KU + (ku0) + lc * 4); \
        cp16(&Als[(stage) * 2048 + SWZ(lrow, lc)], Al + (size_t)(m0 + lrow) * KU + (ku0) + lc * 4);           \
        cp16(&Als[(stage) * 2048 + SWZ(lrow + 64, lc)], Al + (size_t)(m0 + lrow + 64) * KU + (ku0) + lc * 4); \
        cp16(&Whs[(stage) * 2048 + SWZ(lrow, lc)], Wh + (size_t)(n0 + lrow) * KU + (ku0) + lc * 4);           \
        cp16(&Whs[(stage) * 2048 + SWZ(lrow + 64, lc)], Wh + (size_t)(n0 + lrow + 64) * KU + (ku0) + lc * 4); \
        cp16(&Wls[(stage) * 2048 + SWZ(lrow, lc)], Wl + (size_t)(n0 + lrow) * KU + (ku0) + lc * 4);           \
        cp16(&Wls[(stage) * 2048 + SWZ(lrow + 64, lc)], Wl + (size_t)(n0 + lrow + 64) * KU + (ku0) + lc * 4); \
        CP_COMMIT();                                                              \
    } while (0)

    G_LOAD(0, 0);
    G_LOAD(1, 16);

    int sidx = 0;  // i % 3
    for (int i = 0; i < nk; i++) {
        if (i < nk - 1) { CP_WAIT(1); } else { CP_WAIT(0); }
        __syncthreads();   // stage i visible; all warps done reading stage i-1
        if (i + 2 < nk) {
            int ns = sidx + 2; if (ns >= 3) ns -= 3;
            G_LOAD(ns, (i + 2) << 4);
        }
        const unsigned* Ahb = Ahs + sidx * 2048;
        const unsigned* Alb = Als + sidx * 2048;
        const unsigned* Whb = Whs + sidx * 2048;
        const unsigned* Wlb = Wls + sidx * 2048;
#pragma unroll
        for (int kt = 0; kt < 2; kt++) {
            unsigned ah[2][4], al[2][4];
#pragma unroll
            for (int mi = 0; mi < 2; mi++) {
                int row = wm * 32 + mi * 16 + a_r;
                int ch = kt * 2 + a_ch;
                ldsm4(ah[mi][0], ah[mi][1], ah[mi][2], ah[mi][3], &Ahb[SWZ(row, ch)]);
                ldsm4(al[mi][0], al[mi][1], al[mi][2], al[mi][3], &Alb[SWZ(row, ch)]);
            }
            unsigned bh[2][4], bl[2][4];
            {
                int row = wn * 64 + b_r;
                int ch = kt * 2 + b_ch;
                ldsm4(bh[0][0], bh[0][1], bh[0][2], bh[0][3], &Whb[SWZ(row, ch)]);
                ldsm4(bl[0][0], bl[0][1], bl[0][2], bl[0][3], &Wlb[SWZ(row, ch)]);
            }
#pragma unroll
            for (int jp = 0; jp < 4; jp++) {
                int cur = jp & 1;
                if (jp < 3) {
                    int row = wn * 64 + (jp + 1) * 16 + b_r;
                    int ch = kt * 2 + b_ch;
                    ldsm4(bh[cur ^ 1][0], bh[cur ^ 1][1], bh[cur ^ 1][2], bh[cur ^ 1][3],
                          &Whb[SWZ(row, ch)]);
                    ldsm4(bl[cur ^ 1][0], bl[cur ^ 1][1], bl[cur ^ 1][2], bl[cur ^ 1][3],
                          &Wlb[SWZ(row, ch)]);
                }
#pragma unroll
                for (int mi = 0; mi < 2; mi++) {
                    mma16(acc[mi][jp * 2], ah[mi], bh[cur]);
                    mma16(acc[mi][jp * 2], ah[mi], bl[cur]);
                    mma16(acc[mi][jp * 2], al[mi], bh[cur]);
                    mma16(acc[mi][jp * 2 + 1], ah[mi], bh[cur] + 2);
                    mma16(acc[mi][jp * 2 + 1], ah[mi], bl[cur] + 2);
                    mma16(acc[mi][jp * 2 + 1], al[mi], bh[cur] + 2);
                }
            }
        }
        sidx++; if (sidx == 3) sidx = 0;
    }
#pragma unroll
    for (int j = 0; j < 8; j++) {
        int col = n0 + wn * 64 + j * 8 + tg * 2;
        float2 bv = *(const float2*)(bias + col);
#pragma unroll
        for (int mi = 0; mi < 2; mi++) {
            int row = m0 + wm * 32 + mi * 16 + g;
            float2 o0 = make_float2(acc[mi][j][0] + bv.x, acc[mi][j][1] + bv.y);
            float2 o1 = make_float2(acc[mi][j][2] + bv.x, acc[mi][j][3] + bv.y);
            *(float2*)(C + (size_t)row * Nn + col) = o0;
            *(float2*)(C + (size_t)(row + 8) * Nn + col) = o1;
        }
    }
}

// ---------------- reorg: normalize q/k, bf16-split+pack, v tf32 ----------------
__global__ void reorg_kernel(const float* __restrict__ qe) {
    int wg = blockIdx.x * 8 + (threadIdx.x >> 5);
    int lane = threadIdx.x & 31;
    int h = wg & 15;
    int bn = wg >> 4;
    int b = bn >> 10;
    int n = bn & 1023;
    const float* base = g_qkv + (size_t)bn * (3 * DIMC);
    float q = base[h * HD + lane];
    float k = base[DIMC + h * HD + lane];
    float v = base[2 * DIMC + h * HD + lane];

    float s = q * q;
#pragma unroll
    for (int off = 16; off >= 1; off >>= 1) s += __shfl_xor_sync(0xffffffffu, s, off);
    float qn = q / fmaxf(sqrtf(s), 1e-12f);
    qn = (qn + qe[h * HD + lane]) * g_scale[h];

    s = k * k;
#pragma unroll
    for (int off = 16; off >= 1; off >>= 1) s += __shfl_xor_sync(0xffffffffu, s, off);
    float kn = k / fmaxf(sqrtf(s), 1e-12f);

    __nv_bfloat16 qbh = __float2bfloat16_rn(qn);
    unsigned qhu = (unsigned)__bfloat16_as_ushort(qbh);
    unsigned qlu = (unsigned)__bfloat16_as_ushort(__float2bfloat16_rn(qn - __bfloat162float(qbh)));
    __nv_bfloat16 kbh = __float2bfloat16_rn(kn);
    unsigned khu = (unsigned)__bfloat16_as_ushort(kbh);
    unsigned klu = (unsigned)__bfloat16_as_ushort(__float2bfloat16_rn(kn - __bfloat162float(kbh)));

    unsigned qho = __shfl_down_sync(0xffffffffu, qhu, 1);
    unsigned qlo = __shfl_down_sync(0xffffffffu, qlu, 1);
    unsigned kho = __shfl_down_sync(0xffffffffu, khu, 1);
    unsigned klo = __shfl_down_sync(0xffffffffu, klu, 1);

    size_t rbase = ((size_t)(b * NH + h) * NTOK + n) * (HD / 2);
    if ((lane & 1) == 0) {
        int c = lane >> 1;
        g_qh[rbase + c] = qhu | (qho << 16);
        g_ql[rbase + c] = qlu | (qlo << 16);
        g_kh[rbase + c] = khu | (kho << 16);
        g_kl[rbase + c] = klu | (klo << 16);
    }
    g_vt[((size_t)(b * NH + h) * NTOK + n) * HD + lane] = tf32_rna(v);
}

// ---------------- attention v10: fixed-max softmax, pipelined ldmatrix ---------
// grid (B, N/128, H), 256 threads, 128 queries/block, key tiles 64.
#define ATTN_SMEM ((2560 + 2560 + 4608 + 9216 + 8704) * 4)
__global__ __launch_bounds__(256, 2) void attn10_kernel() {
    extern __shared__ unsigned smu[];
    unsigned* Khs = smu;                     // [2][1280]
    unsigned* Kls = smu + 2560;
    unsigned* Vs  = smu + 5120;              // [2][2304]
    __half*  BBh = (__half*)(smu + 9728);    // [2][128*72]
    unsigned* Pb = smu + 9728 + 9216;        // [128][68]

    int b = blockIdx.x, qt = blockIdx.y, h = blockIdx.z;
    int tid = threadIdx.x;
    int w = tid >> 5, lane = tid & 31;
    int g = lane >> 2, tg = lane & 3;

    size_t bh16 = (size_t)(b * NH + h) * NTOK * (HD / 2);
    const unsigned* qhb = g_qh + bh16 + (size_t)qt * 128 * (HD / 2);
    const unsigned* qlb = g_ql + bh16 + (size_t)qt * 128 * (HD / 2);
    const unsigned* khb = g_kh + bh16;
    const unsigned* klb = g_kl + bh16;
    const unsigned* vtb = g_vt + (size_t)(b * NH + h) * NTOK * HD;
    const __half* bbh = g_biash + ((size_t)h * NTOK + qt * 128) * NTOK;

    int krow = tid >> 2, kch = (tid & 3) * 4;
    int vrow = tid >> 3, vch = (tid & 7) * 4;
    int brow = tid >> 3, bch = (tid & 7) * 8;
    int b_r = (lane >> 4) * 8 + (lane & 7), b_c = ((lane >> 3) & 1) * 4;
#define KVB_LOAD(stage, mt_)                                                      \
    do {                                                                          \
        cp16(&Khs[(stage) * 1280 + krow * 20 + kch], khb + (size_t)((mt_) * 64 + krow) * 16 + kch); \
        cp16(&Kls[(stage) * 1280 + krow * 20 + kch], klb + (size_t)((mt_) * 64 + krow) * 16 + kch); \
        cp16(&Vs[(stage) * 2304 + vrow * 36 + vch], vtb + (size_t)((mt_) * 64 + vrow) * 32 + vch);  \
        cp16(&Vs[(stage) * 2304 + (vrow + 32) * 36 + vch], vtb + (size_t)((mt_) * 64 + vrow + 32) * 32 + vch); \
        _Pragma("unroll")                                                         \
        for (int p = 0; p < 4; p++) {                                             \
            int row = brow + p * 32;                                              \
            cp16(&BBh[(stage) * 9216 + row * 72 + bch],                           \
                 bbh + (size_t)row * NTOK + (mt_) * 64 + bch);                    \
        }                                                                         \
        CP_COMMIT();                                                              \
    } while (0)

    KVB_LOAD(0, 0);

    unsigned Qh[2][4], Ql[2][4];
    int r = w * 16 + g;
#pragma unroll
    for (int kt = 0; kt < 2; kt++) {
        int c = kt * 8 + tg;
        Qh[kt][0] = qhb[r * 16 + c];           Ql[kt][0] = qlb[r * 16 + c];
        Qh[kt][1] = qhb[(r + 8) * 16 + c];     Ql[kt][1] = qlb[(r + 8) * 16 + c];
        Qh[kt][2] = qhb[r * 16 + c + 4];       Ql[kt][2] = qlb[r * 16 + c + 4];
        Qh[kt][3] = qhb[(r + 8) * 16 + c + 4]; Ql[kt][3] = qlb[(r + 8) * 16 + c + 4];
    }

    float ps0 = 0.0f, ps1 = 0.0f;   // thread-partial exp sums (reduced at end)
    float O[4][4];
#pragma unroll
    for (int j = 0; j < 4; j++)
#pragma unroll
        for (int c = 0; c < 4; c++) O[j][c] = 0.0f;

    for (int mt = 0; mt < 16; mt++) {
        int s = mt & 1;
        CP_WAIT(0);
        __syncthreads();   // (A) tile mt visible; all warps done with PV(mt-1)
        if (mt + 1 < 16) KVB_LOAD(s ^ 1, mt + 1);

        // QK^T: 3xBF16, B fragments double-buffered across (kt,jp)
        float S[8][4];
#pragma unroll
        for (int j = 0; j < 8; j++)
#pragma unroll
            for (int c = 0; c < 4; c++) S[j][c] = 0.0f;
        const unsigned* Khb = Khs + s * 1280;
        const unsigned* Klb = Kls + s * 1280;
        unsigned bh2[2][4], bl2[2][4];
        {
            int row = b_r, col = b_c;
            ldsm4(bh2[0][0], bh2[0][1], bh2[0][2], bh2[0][3], &Khb[row * 20 + col]);
            ldsm4(bl2[0][0], bl2[0][1], bl2[0][2], bl2[0][3], &Klb[row * 20 + col]);
        }
#pragma unroll
        for (int u = 0; u < 8; u++) {      // u = kt*4 + jp
            int kt = u >> 2, jp = u & 3;
            int cur = u & 1;
            if (u < 7) {
                int nkt = (u + 1) >> 2, njp = (u + 1) & 3;
                int row = njp * 16 + b_r;
                int col = nkt * 8 + b_c;
                ldsm4(bh2[cur ^ 1][0], bh2[cur ^ 1][1], bh2[cur ^ 1][2], bh2[cur ^ 1][3],
                      &Khb[row * 20 + col]);
                ldsm4(bl2[cur ^ 1][0], bl2[cur ^ 1][1], bl2[cur ^ 1][2], bl2[cur ^ 1][3],
                      &Klb[row * 20 + col]);
            }
            mma16(S[jp * 2], Qh[kt], bh2[cur]);
            mma16(S[jp * 2], Qh[kt], bl2[cur]);
            mma16(S[jp * 2], Ql[kt], bh2[cur]);
            mma16(S[jp * 2 + 1], Qh[kt], bh2[cur] + 2);
            mma16(S[jp * 2 + 1], Qh[kt], bl2[cur] + 2);
            mma16(S[jp * 2 + 1], Ql[kt], bh2[cur] + 2);
        }
        // bias add + fixed-shift exp (softmax is shift-invariant; |S| <= ~33)
        const __half* Bb = BBh + s * 9216;
#pragma unroll
        for (int j = 0; j < 8; j++) {
            float2 b0 = __half22float2(*(const __half2*)(Bb + r * 72 + j * 8 + tg * 2));
            float2 b1 = __half22float2(*(const __half2*)(Bb + (r + 8) * 72 + j * 8 + tg * 2));
            S[j][0] = __expf(S[j][0] + b0.x - MFIX);
            S[j][1] = __expf(S[j][1] + b0.y - MFIX);
            S[j][2] = __expf(S[j][2] + b1.x - MFIX);
            S[j][3] = __expf(S[j][3] + b1.y - MFIX);
            ps0 += S[j][0] + S[j][1];
            ps1 += S[j][2] + S[j][3];
        }
        // store P (tf32 bits)
#pragma unroll
        for (int j = 0; j < 8; j++) {
            uint2 p0 = make_uint2(tf32_rna(S[j][0]), tf32_rna(S[j][1]));
            uint2 p1 = make_uint2(tf32_rna(S[j][2]), tf32_rna(S[j][3]));
            *(uint2*)(Pb + r * 68 + j * 8 + tg * 2) = p0;
            *(uint2*)(Pb + (r + 8) * 68 + j * 8 + tg * 2) = p1;
        }
        __syncthreads();   // (B) P visible
        // P @ V (TF32 1x), unnormalized accumulate
        const unsigned* Vb = Vs + s * 2304;
#pragma unroll
        for (int kt = 0; kt < 8; kt++) {
            int kc = kt * 8 + tg;
            unsigned a[4] = {Pb[r * 68 + kc], Pb[(r + 8) * 68 + kc],
                             Pb[r * 68 + kc + 4], Pb[(r + 8) * 68 + kc + 4]};
#pragma unroll
            for (int j = 0; j < 4; j++) {
                unsigned bb[2] = {Vb[kc * 36 + j * 8 + g], Vb[(kc + 4) * 36 + j * 8 + g]};
                mma8t(O[j], a, bb);
            }
        }
    }
    // final l reduction (quad) + epilogue: pack bf16 hi/lo pairs for proj GEMM
    ps0 += __shfl_xor_sync(0xffffffffu, ps0, 1);
    ps0 += __shfl_xor_sync(0xffffffffu, ps0, 2);
    ps1 += __shfl_xor_sync(0xffffffffu, ps1, 1);
    ps1 += __shfl_xor_sync(0xffffffffu, ps1, 2);
    float inv0 = 1.0f / ps0, inv1 = 1.0f / ps1;
    int q0r = qt * 128 + w * 16 + g;
    size_t row0 = (size_t)b * NTOK + q0r;
    int colbase = h * 16;
#pragma unroll
    for (int j = 0; j < 4; j++) {
        unsigned hw, lw;
        bf16_split2(O[j][0] * inv0, O[j][1] * inv0, hw, lw);
        g_oh[row0 * 256 + colbase + j * 4 + tg] = hw;
        g_ol[row0 * 256 + colbase + j * 4 + tg] = lw;
        bf16_split2(O[j][2] * inv1, O[j][3] * inv1, hw, lw);
        g_oh[(row0 + 8) * 256 + colbase + j * 4 + tg] = hw;
        g_ol[(row0 + 8) * 256 + colbase + j * 4 + tg] = lw;
    }
}

// ---------------- launcher ---------------------------------------------------
extern "C" void kernel_launch(void* const* d_in, const int* in_sizes, int n_in,
                              void* d_out, int out_size) {
    const float* x      = (const float*)d_in[0];
    const int*   rpi    = (const int*)d_in[3];
    const float* table  = (const float*)d_in[4];
    const float* qkv_w  = (const float*)d_in[5];
    const float* qkv_b  = (const float*)d_in[6];
    const float* proj_w = (const float*)d_in[7];
    const float* proj_b = (const float*)d_in[8];
    const float* temp   = (const float*)d_in[9];
    const float* qe     = (const float*)d_in[10];
    const float* fc1w   = (const float*)d_in[11];
    const float* fc1b   = (const float*)d_in[12];
    const float* fc2w   = (const float*)d_in[13];
    const float* fc2b   = (const float*)d_in[14];
    float* out = (float*)d_out;

    float* p_qkv;  cudaGetSymbolAddress((void**)&p_qkv,  g_qkv);
    unsigned* p_wh; cudaGetSymbolAddress((void**)&p_wh, g_wh);
    unsigned* p_wl; cudaGetSymbolAddress((void**)&p_wl, g_wl);
    unsigned* p_xh; cudaGetSymbolAddress((void**)&p_xh, g_xh);
    unsigned* p_xl; cudaGetSymbolAddress((void**)&p_xl, g_xl);
    unsigned* p_oh; cudaGetSymbolAddress((void**)&p_oh, g_oh);
    unsigned* p_ol; cudaGetSymbolAddress((void**)&p_ol, g_ol);

    static int attr_set = 0;
    if (!attr_set) {
        cudaFuncSetAttribute(attn10_kernel, cudaFuncAttributeMaxDynamicSharedMemorySize,
                             ATTN_SMEM);
        cudaFuncSetAttribute(gemm3b, cudaFuncAttributeMaxDynamicSharedMemorySize,
                             GEMM_SMEM);
        attr_set = 1;
    }

    split_kernel<<<(NW2 + NX2) / 256, 256>>>(qkv_w, proj_w, x);
    cpb_kernel<<<TABLE_SZ, 512>>>(table, fc1w, fc1b, fc2w, fc2b, temp);
    bias_kernel<<<NTOK, 256>>>(rpi);
    {
        dim3 grid(3 * DIMC / 128, BATCH * NTOK / 128);
        gemm3b<<<grid, 256, GEMM_SMEM>>>(p_xh, p_xl, p_wh, p_wl, qkv_b, p_qkv,
                                         BATCH * NTOK, 3 * DIMC, DIMC);
    }
    reorg_kernel<<<BATCH * NTOK * NH / 8, 256>>>(qe);
    {
        dim3 grid(BATCH, NTOK / 128, NH);
        attn10_kernel<<<grid, 256, ATTN_SMEM>>>();
    }
    {
        dim3 grid(DIMC / 128, BATCH * NTOK / 128);
        gemm3b<<<grid, 256, GEMM_SMEM>>>(p_oh, p_ol, p_wh + 3 * DIMC * DIMC / 2,
                                         p_wl + 3 * DIMC * DIMC / 2, proj_b, out,
                                         BATCH * NTOK, DIMC, DIMC);
    }
}

// round 11
// speedup vs baseline: 1.0207x; 1.0207x over previous
#include <cuda_runtime.h>
#include <cuda_bf16.h>
#include <cuda_fp16.h>
#include <math.h>

// Problem constants
#define BATCH 8
#define NTOK 1024
#define DIMC 512
#define NH 16
#define HD 32
#define TABLE_SZ 3969
#define SEQ_SCALE 6.93147180559945309f  // ln(1024)
#define MFIX 33.0f                      // fixed softmax shift (|logit| <= ~33)

// ---------------- scratch (device globals; no allocation allowed) -------------
__device__ float g_scale[NH];
__device__ float g_t[TABLE_SZ * NH];
__device__ __half g_biash[NH * NTOK * NTOK];            // [h][n][m] 32MB fp16
__device__ float g_qkv[BATCH * NTOK * 3 * DIMC];        // 50MB
__device__ unsigned g_qh[BATCH * NH * NTOK * HD / 2];   // q hi, packed bf16 pairs
__device__ unsigned g_ql[BATCH * NH * NTOK * HD / 2];   // q lo
__device__ unsigned g_kh[BATCH * NH * NTOK * HD / 2];   // k hi
__device__ unsigned g_kl[BATCH * NH * NTOK * HD / 2];   // k lo
__device__ unsigned g_vt[BATCH * NH * NTOK * HD];       // v tf32
__device__ unsigned g_oh[BATCH * NTOK * DIMC / 2];      // attn out hi (bf16 pairs)
__device__ unsigned g_ol[BATCH * NTOK * DIMC / 2];      // attn out lo
__device__ unsigned g_xh[BATCH * NTOK * DIMC / 2];      // x hi
__device__ unsigned g_xl[BATCH * NTOK * DIMC / 2];      // x lo
__device__ unsigned g_wh[(3 * DIMC + DIMC) * DIMC / 2]; // W hi (qkv then proj)
__device__ unsigned g_wl[(3 * DIMC + DIMC) * DIMC / 2]; // W lo

// ---------------- helpers -----------------------------------------------------
__device__ __forceinline__ unsigned tf32_rna(float x) {
    unsigned r; asm("cvt.rna.tf32.f32 %0, %1;" : "=r"(r) : "f"(x)); return r;
}
__device__ __forceinline__ void bf16_split2(float e, float o, unsigned& hi, unsigned& lo) {
    __nv_bfloat162 h2 = __floats2bfloat162_rn(e, o);
    hi = *(unsigned*)&h2;
    float re = e - __bfloat162float(h2.x);
    float ro = o - __bfloat162float(h2.y);
    __nv_bfloat162 l2 = __floats2bfloat162_rn(re, ro);
    lo = *(unsigned*)&l2;
}
__device__ __forceinline__ void mma16(float* c, const unsigned* a, const unsigned* b) {
    asm volatile("mma.sync.aligned.m16n8k16.row.col.f32.bf16.bf16.f32 "
                 "{%0,%1,%2,%3}, {%4,%5,%6,%7}, {%8,%9}, {%0,%1,%2,%3};"
                 : "+f"(c[0]), "+f"(c[1]), "+f"(c[2]), "+f"(c[3])
                 : "r"(a[0]), "r"(a[1]), "r"(a[2]), "r"(a[3]),
                   "r"(b[0]), "r"(b[1]));
}
__device__ __forceinline__ void mma8t(float* c, const unsigned* a, const unsigned* b) {
    asm volatile("mma.sync.aligned.m16n8k8.row.col.f32.tf32.tf32.f32 "
                 "{%0,%1,%2,%3}, {%4,%5,%6,%7}, {%8,%9}, {%0,%1,%2,%3};"
                 : "+f"(c[0]), "+f"(c[1]), "+f"(c[2]), "+f"(c[3])
                 : "r"(a[0]), "r"(a[1]), "r"(a[2]), "r"(a[3]),
                   "r"(b[0]), "r"(b[1]));
}
__device__ __forceinline__ void ldsm4(unsigned& r0, unsigned& r1, unsigned& r2,
                                      unsigned& r3, const void* p) {
    unsigned a = (unsigned)__cvta_generic_to_shared(p);
    asm volatile("ldmatrix.sync.aligned.m8n8.x4.shared.b16 {%0,%1,%2,%3}, [%4];"
                 : "=r"(r0), "=r"(r1), "=r"(r2), "=r"(r3) : "r"(a));
}
__device__ __forceinline__ void cp16(void* sdst, const void* gsrc) {
    unsigned u = (unsigned)__cvta_generic_to_shared(sdst);
    asm volatile("cp.async.ca.shared.global [%0], [%1], 16;" :: "r"(u), "l"(gsrc));
}
#define CP_COMMIT() asm volatile("cp.async.commit_group;")
#define CP_WAIT(n)  asm volatile("cp.async.wait_group %0;" :: "n"(n))

// ---------------- fused split: weights + x (bf16 hi/lo pairs) ------------------
#define NW2 (4 * DIMC * DIMC / 2)
#define NX2 (BATCH * NTOK * DIMC / 2)
__global__ void split_kernel(const float* __restrict__ qkvw,
                             const float* __restrict__ projw,
                             const float* __restrict__ x) {
    int i = blockIdx.x * 256 + threadIdx.x;
    unsigned h, l;
    if (i < NW2) {
        int nq2 = 3 * DIMC * DIMC / 2;
        float2 v = (i < nq2) ? ((const float2*)qkvw)[i] : ((const float2*)projw)[i - nq2];
        bf16_split2(v.x, v.y, h, l);
        g_wh[i] = h; g_wl[i] = l;
    } else {
        int j = i - NW2;
        float2 v = ((const float2*)x)[j];
        bf16_split2(v.x, v.y, h, l);
        g_xh[j] = h; g_xl[j] = l;
    }
}

// ---------------- CPB MLP t[r][h] (+ fused temperature scale) -----------------
__global__ void cpb_kernel(const float* __restrict__ table,
                           const float* __restrict__ fc1w,
                           const float* __restrict__ fc1b,
                           const float* __restrict__ fc2w,
                           const float* __restrict__ fc2b,
                           const float* __restrict__ temp) {
    __shared__ float hid[512];
    int r = blockIdx.x;
    int j = threadIdx.x;
    if (r == 0 && j < NH) {
        float t = temp[j];
        float sp = (t > 20.0f) ? t : log1pf(expf(t));
        g_scale[j] = sp * SEQ_SCALE;
    }
    float c0 = table[r * 2 + 0];
    float c1 = table[r * 2 + 1];
    float hv = c0 * fc1w[j * 2 + 0] + c1 * fc1w[j * 2 + 1] + fc1b[j];
    hid[j] = fmaxf(hv, 0.0f);
    __syncthreads();
    int w = j >> 5;
    int lane = j & 31;
    float acc = 0.0f;
#pragma unroll
    for (int kk = lane; kk < 512; kk += 32) acc += hid[kk] * fc2w[w * 512 + kk];
#pragma unroll
    for (int off = 16; off >= 1; off >>= 1) acc += __shfl_xor_sync(0xffffffffu, acc, off);
    if (lane == 0) g_t[r * NH + w] = acc + fc2b[w];
}

// ---------------- bias gather  biash[h][n][m] = half(t[rpi[n][m]][h]) ---------
__global__ void bias_kernel(const int* __restrict__ rpi) {
    int n = blockIdx.x;
    for (int m = threadIdx.x; m < NTOK; m += blockDim.x) {
        int idx = rpi[n * NTOK + m];
        const float4* tp = (const float4*)(g_t + idx * NH);
        float4 t0 = tp[0], t1 = tp[1], t2 = tp[2], t3 = tp[3];
        float v[16] = {t0.x, t0.y, t0.z, t0.w, t1.x, t1.y, t1.z, t1.w,
                       t2.x, t2.y, t2.z, t2.w, t3.x, t3.y, t3.z, t3.w};
#pragma unroll
        for (int h = 0; h < NH; h++)
            g_biash[((size_t)h * NTOK + n) * NTOK + m] = __float2half(v[h]);
    }
}

// ---------------- 3xBF16 GEMM, cp.async 2-stage, pipelined ldmatrix ------------
// (round-9 version: padded stride-20 smem — measured fastest)
#define GEMM_SMEM (4 * 2 * 128 * 20 * 4)
__global__ __launch_bounds__(256, 2) void gemm3b(const unsigned* __restrict__ Ah,
                                                 const unsigned* __restrict__ Al,
                                                 const unsigned* __restrict__ Wh,
                                                 const unsigned* __restrict__ Wl,
                                                 const float* __restrict__ bias,
                                                 float* __restrict__ C,
                                                 int M, int Nn, int K) {
    extern __shared__ unsigned smg[];
    unsigned* Ahs = smg;               // [2][2560]
    unsigned* Als = smg + 2 * 2560;
    unsigned* Whs = smg + 4 * 2560;
    unsigned* Wls = smg + 6 * 2560;

    int tid = threadIdx.x;
    int wid = tid >> 5, lane = tid & 31;
    int g = lane >> 2, tg = lane & 3;
    int wm = wid & 3, wn = wid >> 2;
    int m0 = blockIdx.y * 128, n0 = blockIdx.x * 128;
    int KU = K >> 1;

    int lrow = tid >> 2, lch = (tid & 3) * 4;
    int a_r = (lane & 15), a_c = (lane >> 4) * 4;              // A ldmatrix map
    int b_r = (lane >> 4) * 8 + (lane & 7), b_c = ((lane >> 3) & 1) * 4;  // B map

    float acc[2][8][4];
#pragma unroll
    for (int mi = 0; mi < 2; mi++)
#pragma unroll
        for (int j = 0; j < 8; j++)
#pragma unroll
            for (int c = 0; c < 4; c++) acc[mi][j][c] = 0.0f;

    int nk = K >> 5;
#define G_LOAD(stage, ku0)                                                        \
    do {                                                                          \
        cp16(&Ahs[(stage) * 2560 + lrow * 20 + lch], Ah + (size_t)(m0 + lrow) * KU + (ku0) + lch);          \
        cp16(&Ahs[(stage) * 2560 + (lrow + 64) * 20 + lch], Ah + (size_t)(m0 + lrow + 64) * KU + (ku0) + lch); \
        cp16(&Als[(stage) * 2560 + lrow * 20 + lch], Al + (size_t)(m0 + lrow) * KU + (ku0) + lch);          \
        cp16(&Als[(stage) * 2560 + (lrow + 64) * 20 + lch], Al + (size_t)(m0 + lrow + 64) * KU + (ku0) + lch); \
        cp16(&Whs[(stage) * 2560 + lrow * 20 + lch], Wh + (size_t)(n0 + lrow) * KU + (ku0) + lch);          \
        cp16(&Whs[(stage) * 2560 + (lrow + 64) * 20 + lch], Wh + (size_t)(n0 + lrow + 64) * KU + (ku0) + lch); \
        cp16(&Wls[(stage) * 2560 + lrow * 20 + lch], Wl + (size_t)(n0 + lrow) * KU + (ku0) + lch);          \
        cp16(&Wls[(stage) * 2560 + (lrow + 64) * 20 + lch], Wl + (size_t)(n0 + lrow + 64) * KU + (ku0) + lch); \
        CP_COMMIT();                                                              \
    } while (0)

    G_LOAD(0, 0);

    for (int i = 0; i < nk; i++) {
        if (i + 1 < nk) {
            G_LOAD((i + 1) & 1, (i + 1) << 4);
            CP_WAIT(1);
        } else {
            CP_WAIT(0);
        }
        __syncthreads();
        int s = i & 1;
        const unsigned* Ahb = Ahs + s * 2560;
        const unsigned* Alb = Als + s * 2560;
        const unsigned* Whb = Whs + s * 2560;
        const unsigned* Wlb = Wls + s * 2560;
#pragma unroll
        for (int kt = 0; kt < 2; kt++) {
            unsigned ah[2][4], al[2][4];
#pragma unroll
            for (int mi = 0; mi < 2; mi++) {
                int row = wm * 32 + mi * 16 + a_r;
                int col = kt * 8 + a_c;
                ldsm4(ah[mi][0], ah[mi][1], ah[mi][2], ah[mi][3], &Ahb[row * 20 + col]);
                ldsm4(al[mi][0], al[mi][1], al[mi][2], al[mi][3], &Alb[row * 20 + col]);
            }
            unsigned bh[2][4], bl[2][4];
            {
                int row = wn * 64 + b_r;
                int col = kt * 8 + b_c;
                ldsm4(bh[0][0], bh[0][1], bh[0][2], bh[0][3], &Whb[row * 20 + col]);
                ldsm4(bl[0][0], bl[0][1], bl[0][2], bl[0][3], &Wlb[row * 20 + col]);
            }
#pragma unroll
            for (int jp = 0; jp < 4; jp++) {
                int cur = jp & 1;
                if (jp < 3) {
                    int row = wn * 64 + (jp + 1) * 16 + b_r;
                    int col = kt * 8 + b_c;
                    ldsm4(bh[cur ^ 1][0], bh[cur ^ 1][1], bh[cur ^ 1][2], bh[cur ^ 1][3],
                          &Whb[row * 20 + col]);
                    ldsm4(bl[cur ^ 1][0], bl[cur ^ 1][1], bl[cur ^ 1][2], bl[cur ^ 1][3],
                          &Wlb[row * 20 + col]);
                }
#pragma unroll
                for (int mi = 0; mi < 2; mi++) {
                    mma16(acc[mi][jp * 2], ah[mi], bh[cur]);
                    mma16(acc[mi][jp * 2], ah[mi], bl[cur]);
                    mma16(acc[mi][jp * 2], al[mi], bh[cur]);
                    mma16(acc[mi][jp * 2 + 1], ah[mi], bh[cur] + 2);
                    mma16(acc[mi][jp * 2 + 1], ah[mi], bl[cur] + 2);
                    mma16(acc[mi][jp * 2 + 1], al[mi], bh[cur] + 2);
                }
            }
        }
        __syncthreads();
    }
#pragma unroll
    for (int j = 0; j < 8; j++) {
        int col = n0 + wn * 64 + j * 8 + tg * 2;
        float2 bv = *(const float2*)(bias + col);
#pragma unroll
        for (int mi = 0; mi < 2; mi++) {
            int row = m0 + wm * 32 + mi * 16 + g;
            float2 o0 = make_float2(acc[mi][j][0] + bv.x, acc[mi][j][1] + bv.y);
            float2 o1 = make_float2(acc[mi][j][2] + bv.x, acc[mi][j][3] + bv.y);
            *(float2*)(C + (size_t)row * Nn + col) = o0;
            *(float2*)(C + (size_t)(row + 8) * Nn + col) = o1;
        }
    }
}

// ---------------- reorg: normalize q/k, bf16-split+pack, v tf32 ----------------
__global__ void reorg_kernel(const float* __restrict__ qe) {
    int wg = blockIdx.x * 8 + (threadIdx.x >> 5);
    int lane = threadIdx.x & 31;
    int h = wg & 15;
    int bn = wg >> 4;
    int b = bn >> 10;
    int n = bn & 1023;
    const float* base = g_qkv + (size_t)bn * (3 * DIMC);
    float q = base[h * HD + lane];
    float k = base[DIMC + h * HD + lane];
    float v = base[2 * DIMC + h * HD + lane];

    float s = q * q;
#pragma unroll
    for (int off = 16; off >= 1; off >>= 1) s += __shfl_xor_sync(0xffffffffu, s, off);
    float qn = q / fmaxf(sqrtf(s), 1e-12f);
    qn = (qn + qe[h * HD + lane]) * g_scale[h];

    s = k * k;
#pragma unroll
    for (int off = 16; off >= 1; off >>= 1) s += __shfl_xor_sync(0xffffffffu, s, off);
    float kn = k / fmaxf(sqrtf(s), 1e-12f);

    __nv_bfloat16 qbh = __float2bfloat16_rn(qn);
    unsigned qhu = (unsigned)__bfloat16_as_ushort(qbh);
    unsigned qlu = (unsigned)__bfloat16_as_ushort(__float2bfloat16_rn(qn - __bfloat162float(qbh)));
    __nv_bfloat16 kbh = __float2bfloat16_rn(kn);
    unsigned khu = (unsigned)__bfloat16_as_ushort(kbh);
    unsigned klu = (unsigned)__bfloat16_as_ushort(__float2bfloat16_rn(kn - __bfloat162float(kbh)));

    unsigned qho = __shfl_down_sync(0xffffffffu, qhu, 1);
    unsigned qlo = __shfl_down_sync(0xffffffffu, qlu, 1);
    unsigned kho = __shfl_down_sync(0xffffffffu, khu, 1);
    unsigned klo = __shfl_down_sync(0xffffffffu, klu, 1);

    size_t rbase = ((size_t)(b * NH + h) * NTOK + n) * (HD / 2);
    if ((lane & 1) == 0) {
        int c = lane >> 1;
        g_qh[rbase + c] = qhu | (qho << 16);
        g_ql[rbase + c] = qlu | (qlo << 16);
        g_kh[rbase + c] = khu | (kho << 16);
        g_kl[rbase + c] = klu | (klo << 16);
    }
    g_vt[((size_t)(b * NH + h) * NTOK + n) * HD + lane] = tf32_rna(v);
}

// ---------------- attention v10: fixed-max softmax, pipelined ldmatrix ---------
// grid (B, N/128, H), 256 threads, 128 queries/block, key tiles 64.
#define ATTN_SMEM ((2560 + 2560 + 4608 + 9216 + 8704) * 4)
__global__ __launch_bounds__(256, 2) void attn10_kernel() {
    extern __shared__ unsigned smu[];
    unsigned* Khs = smu;                     // [2][1280]
    unsigned* Kls = smu + 2560;
    unsigned* Vs  = smu + 5120;              // [2][2304]
    __half*  BBh = (__half*)(smu + 9728);    // [2][128*72]
    unsigned* Pb = smu + 9728 + 9216;        // [128][68]

    int b = blockIdx.x, qt = blockIdx.y, h = blockIdx.z;
    int tid = threadIdx.x;
    int w = tid >> 5, lane = tid & 31;
    int g = lane >> 2, tg = lane & 3;

    size_t bh16 = (size_t)(b * NH + h) * NTOK * (HD / 2);
    const unsigned* qhb = g_qh + bh16 + (size_t)qt * 128 * (HD / 2);
    const unsigned* qlb = g_ql + bh16 + (size_t)qt * 128 * (HD / 2);
    const unsigned* khb = g_kh + bh16;
    const unsigned* klb = g_kl + bh16;
    const unsigned* vtb = g_vt + (size_t)(b * NH + h) * NTOK * HD;
    const __half* bbh = g_biash + ((size_t)h * NTOK + qt * 128) * NTOK;

    int krow = tid >> 2, kch = (tid & 3) * 4;
    int vrow = tid >> 3, vch = (tid & 7) * 4;
    int brow = tid >> 3, bch = (tid & 7) * 8;
    int b_r = (lane >> 4) * 8 + (lane & 7), b_c = ((lane >> 3) & 1) * 4;
#define KVB_LOAD(stage, mt_)                                                      \
    do {                                                                          \
        cp16(&Khs[(stage) * 1280 + krow * 20 + kch], khb + (size_t)((mt_) * 64 + krow) * 16 + kch); \
        cp16(&Kls[(stage) * 1280 + krow * 20 + kch], klb + (size_t)((mt_) * 64 + krow) * 16 + kch); \
        cp16(&Vs[(stage) * 2304 + vrow * 36 + vch], vtb + (size_t)((mt_) * 64 + vrow) * 32 + vch);  \
        cp16(&Vs[(stage) * 2304 + (vrow + 32) * 36 + vch], vtb + (size_t)((mt_) * 64 + vrow + 32) * 32 + vch); \
        _Pragma("unroll")                                                         \
        for (int p = 0; p < 4; p++) {                                             \
            int row = brow + p * 32;                                              \
            cp16(&BBh[(stage) * 9216 + row * 72 + bch],                           \
                 bbh + (size_t)row * NTOK + (mt_) * 64 + bch);                    \
        }                                                                         \
        CP_COMMIT();                                                              \
    } while (0)

    KVB_LOAD(0, 0);

    unsigned Qh[2][4], Ql[2][4];
    int r = w * 16 + g;
#pragma unroll
    for (int kt = 0; kt < 2; kt++) {
        int c = kt * 8 + tg;
        Qh[kt][0] = qhb[r * 16 + c];           Ql[kt][0] = qlb[r * 16 + c];
        Qh[kt][1] = qhb[(r + 8) * 16 + c];     Ql[kt][1] = qlb[(r + 8) * 16 + c];
        Qh[kt][2] = qhb[r * 16 + c + 4];       Ql[kt][2] = qlb[r * 16 + c + 4];
        Qh[kt][3] = qhb[(r + 8) * 16 + c + 4]; Ql[kt][3] = qlb[(r + 8) * 16 + c + 4];
    }

    float ps0 = 0.0f, ps1 = 0.0f;   // thread-partial exp sums (reduced at end)
    float O[4][4];
#pragma unroll
    for (int j = 0; j < 4; j++)
#pragma unroll
        for (int c = 0; c < 4; c++) O[j][c] = 0.0f;

    for (int mt = 0; mt < 16; mt++) {
        int s = mt & 1;
        CP_WAIT(0);
        __syncthreads();   // (A) tile mt visible; all warps done with PV(mt-1)
        if (mt + 1 < 16) KVB_LOAD(s ^ 1, mt + 1);

        // QK^T: 3xBF16, B fragments double-buffered across (kt,jp)
        float S[8][4];
#pragma unroll
        for (int j = 0; j < 8; j++)
#pragma unroll
            for (int c = 0; c < 4; c++) S[j][c] = 0.0f;
        const unsigned* Khb = Khs + s * 1280;
        const unsigned* Klb = Kls + s * 1280;
        unsigned bh2[2][4], bl2[2][4];
        {
            int row = b_r, col = b_c;
            ldsm4(bh2[0][0], bh2[0][1], bh2[0][2], bh2[0][3], &Khb[row * 20 + col]);
            ldsm4(bl2[0][0], bl2[0][1], bl2[0][2], bl2[0][3], &Klb[row * 20 + col]);
        }
#pragma unroll
        for (int u = 0; u < 8; u++) {      // u = kt*4 + jp
            int kt = u >> 2, jp = u & 3;
            int cur = u & 1;
            if (u < 7) {
                int nkt = (u + 1) >> 2, njp = (u + 1) & 3;
                int row = njp * 16 + b_r;
                int col = nkt * 8 + b_c;
                ldsm4(bh2[cur ^ 1][0], bh2[cur ^ 1][1], bh2[cur ^ 1][2], bh2[cur ^ 1][3],
                      &Khb[row * 20 + col]);
                ldsm4(bl2[cur ^ 1][0], bl2[cur ^ 1][1], bl2[cur ^ 1][2], bl2[cur ^ 1][3],
                      &Klb[row * 20 + col]);
            }
            mma16(S[jp * 2], Qh[kt], bh2[cur]);
            mma16(S[jp * 2], Qh[kt], bl2[cur]);
            mma16(S[jp * 2], Ql[kt], bh2[cur]);
            mma16(S[jp * 2 + 1], Qh[kt], bh2[cur] + 2);
            mma16(S[jp * 2 + 1], Qh[kt], bl2[cur] + 2);
            mma16(S[jp * 2 + 1], Ql[kt], bh2[cur] + 2);
        }
        // bias add + fixed-shift exp (softmax is shift-invariant; |S| <= ~33)
        const __half* Bb = BBh + s * 9216;
#pragma unroll
        for (int j = 0; j < 8; j++) {
            float2 b0 = __half22float2(*(const __half2*)(Bb + r * 72 + j * 8 + tg * 2));
            float2 b1 = __half22float2(*(const __half2*)(Bb + (r + 8) * 72 + j * 8 + tg * 2));
            S[j][0] = __expf(S[j][0] + b0.x - MFIX);
            S[j][1] = __expf(S[j][1] + b0.y - MFIX);
            S[j][2] = __expf(S[j][2] + b1.x - MFIX);
            S[j][3] = __expf(S[j][3] + b1.y - MFIX);
            ps0 += S[j][0] + S[j][1];
            ps1 += S[j][2] + S[j][3];
        }
        // store P (tf32 bits)
#pragma unroll
        for (int j = 0; j < 8; j++) {
            uint2 p0 = make_uint2(tf32_rna(S[j][0]), tf32_rna(S[j][1]));
            uint2 p1 = make_uint2(tf32_rna(S[j][2]), tf32_rna(S[j][3]));
            *(uint2*)(Pb + r * 68 + j * 8 + tg * 2) = p0;
            *(uint2*)(Pb + (r + 8) * 68 + j * 8 + tg * 2) = p1;
        }
        __syncthreads();   // (B) P visible
        // P @ V (TF32 1x), unnormalized accumulate
        const unsigned* Vb = Vs + s * 2304;
#pragma unroll
        for (int kt = 0; kt < 8; kt++) {
            int kc = kt * 8 + tg;
            unsigned a[4] = {Pb[r * 68 + kc], Pb[(r + 8) * 68 + kc],
                             Pb[r * 68 + kc + 4], Pb[(r + 8) * 68 + kc + 4]};
#pragma unroll
            for (int j = 0; j < 4; j++) {
                unsigned bb[2] = {Vb[kc * 36 + j * 8 + g], Vb[(kc + 4) * 36 + j * 8 + g]};
                mma8t(O[j], a, bb);
            }
        }
    }
    // final l reduction (quad) + epilogue: pack bf16 hi/lo pairs for proj GEMM
    ps0 += __shfl_xor_sync(0xffffffffu, ps0, 1);
    ps0 += __shfl_xor_sync(0xffffffffu, ps0, 2);
    ps1 += __shfl_xor_sync(0xffffffffu, ps1, 1);
    ps1 += __shfl_xor_sync(0xffffffffu, ps1, 2);
    float inv0 = 1.0f / ps0, inv1 = 1.0f / ps1;
    int q0r = qt * 128 + w * 16 + g;
    size_t row0 = (size_t)b * NTOK + q0r;
    int colbase = h * 16;
#pragma unroll
    for (int j = 0; j < 4; j++) {
        unsigned hw, lw;
        bf16_split2(O[j][0] * inv0, O[j][1] * inv0, hw, lw);
        g_oh[row0 * 256 + colbase + j * 4 + tg] = hw;
        g_ol[row0 * 256 + colbase + j * 4 + tg] = lw;
        bf16_split2(O[j][2] * inv1, O[j][3] * inv1, hw, lw);
        g_oh[(row0 + 8) * 256 + colbase + j * 4 + tg] = hw;
        g_ol[(row0 + 8) * 256 + colbase + j * 4 + tg] = lw;
    }
}

// ---------------- launcher ---------------------------------------------------
extern "C" void kernel_launch(void* const* d_in, const int* in_sizes, int n_in,
                              void* d_out, int out_size) {
    const float* x      = (const float*)d_in[0];
    const int*   rpi    = (const int*)d_in[3];
    const float* table  = (const float*)d_in[4];
    const float* qkv_w  = (const float*)d_in[5];
    const float* qkv_b  = (const float*)d_in[6];
    const float* proj_w = (const float*)d_in[7];
    const float* proj_b = (const float*)d_in[8];
    const float* temp   = (const float*)d_in[9];
    const float* qe     = (const float*)d_in[10];
    const float* fc1w   = (const float*)d_in[11];
    const float* fc1b   = (const float*)d_in[12];
    const float* fc2w   = (const float*)d_in[13];
    const float* fc2b   = (const float*)d_in[14];
    float* out = (float*)d_out;

    float* p_qkv;  cudaGetSymbolAddress((void**)&p_qkv,  g_qkv);
    unsigned* p_wh; cudaGetSymbolAddress((void**)&p_wh, g_wh);
    unsigned* p_wl; cudaGetSymbolAddress((void**)&p_wl, g_wl);
    unsigned* p_xh; cudaGetSymbolAddress((void**)&p_xh, g_xh);
    unsigned* p_xl; cudaGetSymbolAddress((void**)&p_xl, g_xl);
    unsigned* p_oh; cudaGetSymbolAddress((void**)&p_oh, g_oh);
    unsigned* p_ol; cudaGetSymbolAddress((void**)&p_ol, g_ol);

    static int attr_set = 0;
    if (!attr_set) {
        cudaFuncSetAttribute(attn10_kernel, cudaFuncAttributeMaxDynamicSharedMemorySize,
                             ATTN_SMEM);
        cudaFuncSetAttribute(gemm3b, cudaFuncAttributeMaxDynamicSharedMemorySize,
                             GEMM_SMEM);
        attr_set = 1;
    }

    split_kernel<<<(NW2 + NX2) / 256, 256>>>(qkv_w, proj_w, x);
    cpb_kernel<<<TABLE_SZ, 512>>>(table, fc1w, fc1b, fc2w, fc2b, temp);
    bias_kernel<<<NTOK, 256>>>(rpi);
    {
        dim3 grid(3 * DIMC / 128, BATCH * NTOK / 128);
        gemm3b<<<grid, 256, GEMM_SMEM>>>(p_xh, p_xl, p_wh, p_wl, qkv_b, p_qkv,
                                         BATCH * NTOK, 3 * DIMC, DIMC);
    }
    reorg_kernel<<<BATCH * NTOK * NH / 8, 256>>>(qe);
    {
        dim3 grid(BATCH, NTOK / 128, NH);
        attn10_kernel<<<grid, 256, ATTN_SMEM>>>();
    }
    {
        dim3 grid(DIMC / 128, BATCH * NTOK / 128);
        gemm3b<<<grid, 256, GEMM_SMEM>>>(p_oh, p_ol, p_wh + 3 * DIMC * DIMC / 2,
                                         p_wl + 3 * DIMC * DIMC / 2, proj_b, out,
                                         BATCH * NTOK, DIMC, DIMC);
    }
}

// round 13
// speedup vs baseline: 1.2748x; 1.2490x over previous
#include <cuda_runtime.h>
#include <cuda_bf16.h>
#include <cuda_fp16.h>
#include <math.h>

// Problem constants
#define BATCH 8
#define NTOK 1024
#define DIMC 512
#define NH 16
#define HD 32
#define TABLE_SZ 3969
#define SEQ_SCALE 6.93147180559945309f  // ln(1024)

// ---------------- scratch (device globals; no allocation allowed) -------------
__device__ float g_scale[NH];
__device__ float g_t[TABLE_SZ * NH];
__device__ __half g_biash[NH * NTOK * NTOK];            // [h][n][m] 32MB fp16
__device__ float g_qkv[BATCH * NTOK * 3 * DIMC];        // 50MB
__device__ unsigned g_qh[BATCH * NH * NTOK * HD / 2];   // q hi, packed bf16 pairs
__device__ unsigned g_ql[BATCH * NH * NTOK * HD / 2];   // q lo
__device__ unsigned g_kh[BATCH * NH * NTOK * HD / 2];   // k hi
__device__ unsigned g_kl[BATCH * NH * NTOK * HD / 2];   // k lo
__device__ unsigned g_vh[BATCH * NH * NTOK * HD / 2];   // v fp16 pairs [key][d]
__device__ unsigned g_oh[BATCH * NTOK * DIMC / 2];      // attn out hi (bf16 pairs)
__device__ unsigned g_ol[BATCH * NTOK * DIMC / 2];      // attn out lo
__device__ unsigned g_xh[BATCH * NTOK * DIMC / 2];      // x hi
__device__ unsigned g_xl[BATCH * NTOK * DIMC / 2];      // x lo
__device__ unsigned g_wh[(3 * DIMC + DIMC) * DIMC / 2]; // W hi (qkv then proj)
__device__ unsigned g_wl[(3 * DIMC + DIMC) * DIMC / 2]; // W lo

// ---------------- helpers -----------------------------------------------------
__device__ __forceinline__ void bf16_split2(float e, float o, unsigned& hi, unsigned& lo) {
    __nv_bfloat162 h2 = __floats2bfloat162_rn(e, o);
    hi = *(unsigned*)&h2;
    float re = e - __bfloat162float(h2.x);
    float ro = o - __bfloat162float(h2.y);
    __nv_bfloat162 l2 = __floats2bfloat162_rn(re, ro);
    lo = *(unsigned*)&l2;
}
__device__ __forceinline__ unsigned h2pack(float e, float o) {
    __half2 h = __floats2half2_rn(e, o);
    return *(unsigned*)&h;
}
__device__ __forceinline__ void mma16(float* c, const unsigned* a, const unsigned* b) {
    asm volatile("mma.sync.aligned.m16n8k16.row.col.f32.bf16.bf16.f32 "
                 "{%0,%1,%2,%3}, {%4,%5,%6,%7}, {%8,%9}, {%0,%1,%2,%3};"
                 : "+f"(c[0]), "+f"(c[1]), "+f"(c[2]), "+f"(c[3])
                 : "r"(a[0]), "r"(a[1]), "r"(a[2]), "r"(a[3]),
                   "r"(b[0]), "r"(b[1]));
}
__device__ __forceinline__ void mma16h(float* c, const unsigned* a, const unsigned* b) {
    asm volatile("mma.sync.aligned.m16n8k16.row.col.f32.f16.f16.f32 "
                 "{%0,%1,%2,%3}, {%4,%5,%6,%7}, {%8,%9}, {%0,%1,%2,%3};"
                 : "+f"(c[0]), "+f"(c[1]), "+f"(c[2]), "+f"(c[3])
                 : "r"(a[0]), "r"(a[1]), "r"(a[2]), "r"(a[3]),
                   "r"(b[0]), "r"(b[1]));
}
__device__ __forceinline__ void ldsm4(unsigned& r0, unsigned& r1, unsigned& r2,
                                      unsigned& r3, const void* p) {
    unsigned a = (unsigned)__cvta_generic_to_shared(p);
    asm volatile("ldmatrix.sync.aligned.m8n8.x4.shared.b16 {%0,%1,%2,%3}, [%4];"
                 : "=r"(r0), "=r"(r1), "=r"(r2), "=r"(r3) : "r"(a));
}
__device__ __forceinline__ void ldsm4t(unsigned& r0, unsigned& r1, unsigned& r2,
                                       unsigned& r3, const void* p) {
    unsigned a = (unsigned)__cvta_generic_to_shared(p);
    asm volatile("ldmatrix.sync.aligned.m8n8.x4.trans.shared.b16 {%0,%1,%2,%3}, [%4];"
                 : "=r"(r0), "=r"(r1), "=r"(r2), "=r"(r3) : "r"(a));
}
__device__ __forceinline__ void cp16(void* sdst, const void* gsrc) {
    unsigned u = (unsigned)__cvta_generic_to_shared(sdst);
    asm volatile("cp.async.ca.shared.global [%0], [%1], 16;" :: "r"(u), "l"(gsrc));
}
#define CP_COMMIT() asm volatile("cp.async.commit_group;")
#define CP_WAIT(n)  asm volatile("cp.async.wait_group %0;" :: "n"(n))

// ---------------- fused split: weights + x (bf16 hi/lo pairs) ------------------
#define NW2 (4 * DIMC * DIMC / 2)
#define NX2 (BATCH * NTOK * DIMC / 2)
__global__ void split_kernel(const float* __restrict__ qkvw,
                             const float* __restrict__ projw,
                             const float* __restrict__ x) {
    int i = blockIdx.x * 256 + threadIdx.x;
    unsigned h, l;
    if (i < NW2) {
        int nq2 = 3 * DIMC * DIMC / 2;
        float2 v = (i < nq2) ? ((const float2*)qkvw)[i] : ((const float2*)projw)[i - nq2];
        bf16_split2(v.x, v.y, h, l);
        g_wh[i] = h; g_wl[i] = l;
    } else {
        int j = i - NW2;
        float2 v = ((const float2*)x)[j];
        bf16_split2(v.x, v.y, h, l);
        g_xh[j] = h; g_xl[j] = l;
    }
}

// ---------------- CPB MLP t[r][h] (+ fused temperature scale) -----------------
__global__ void cpb_kernel(const float* __restrict__ table,
                           const float* __restrict__ fc1w,
                           const float* __restrict__ fc1b,
                           const float* __restrict__ fc2w,
                           const float* __restrict__ fc2b,
                           const float* __restrict__ temp) {
    __shared__ float hid[512];
    int r = blockIdx.x;
    int j = threadIdx.x;
    if (r == 0 && j < NH) {
        float t = temp[j];
        float sp = (t > 20.0f) ? t : log1pf(expf(t));
        g_scale[j] = sp * SEQ_SCALE;
    }
    float c0 = table[r * 2 + 0];
    float c1 = table[r * 2 + 1];
    float hv = c0 * fc1w[j * 2 + 0] + c1 * fc1w[j * 2 + 1] + fc1b[j];
    hid[j] = fmaxf(hv, 0.0f);
    __syncthreads();
    int w = j >> 5;
    int lane = j & 31;
    float acc = 0.0f;
#pragma unroll
    for (int kk = lane; kk < 512; kk += 32) acc += hid[kk] * fc2w[w * 512 + kk];
#pragma unroll
    for (int off = 16; off >= 1; off >>= 1) acc += __shfl_xor_sync(0xffffffffu, acc, off);
    if (lane == 0) g_t[r * NH + w] = acc + fc2b[w];
}

// ---------------- bias gather  biash[h][n][m] = half(t[rpi[n][m]][h]) ---------
__global__ void bias_kernel(const int* __restrict__ rpi) {
    int n = blockIdx.x;
    for (int m = threadIdx.x; m < NTOK; m += blockDim.x) {
        int idx = rpi[n * NTOK + m];
        const float4* tp = (const float4*)(g_t + idx * NH);
        float4 t0 = tp[0], t1 = tp[1], t2 = tp[2], t3 = tp[3];
        float v[16] = {t0.x, t0.y, t0.z, t0.w, t1.x, t1.y, t1.z, t1.w,
                       t2.x, t2.y, t2.z, t2.w, t3.x, t3.y, t3.z, t3.w};
#pragma unroll
        for (int h = 0; h < NH; h++)
            g_biash[((size_t)h * NTOK + n) * NTOK + m] = __float2half(v[h]);
    }
}

// ---------------- 3xBF16 GEMM, cp.async 2-stage, pipelined ldmatrix ------------
#define GEMM_SMEM (4 * 2 * 128 * 20 * 4)
__global__ __launch_bounds__(256, 2) void gemm3b(const unsigned* __restrict__ Ah,
                                                 const unsigned* __restrict__ Al,
                                                 const unsigned* __restrict__ Wh,
                                                 const unsigned* __restrict__ Wl,
                                                 const float* __restrict__ bias,
                                                 float* __restrict__ C,
                                                 int M, int Nn, int K) {
    extern __shared__ unsigned smg[];
    unsigned* Ahs = smg;               // [2][2560]
    unsigned* Als = smg + 2 * 2560;
    unsigned* Whs = smg + 4 * 2560;
    unsigned* Wls = smg + 6 * 2560;

    int tid = threadIdx.x;
    int wid = tid >> 5, lane = tid & 31;
    int g = lane >> 2, tg = lane & 3;
    int wm = wid & 3, wn = wid >> 2;
    int m0 = blockIdx.y * 128, n0 = blockIdx.x * 128;
    int KU = K >> 1;

    int lrow = tid >> 2, lch = (tid & 3) * 4;
    int a_r = (lane & 15), a_c = (lane >> 4) * 4;
    int b_r = (lane >> 4) * 8 + (lane & 7), b_c = ((lane >> 3) & 1) * 4;

    float acc[2][8][4];
#pragma unroll
    for (int mi = 0; mi < 2; mi++)
#pragma unroll
        for (int j = 0; j < 8; j++)
#pragma unroll
            for (int c = 0; c < 4; c++) acc[mi][j][c] = 0.0f;

    int nk = K >> 5;
#define G_LOAD(stage, ku0)                                                        \
    do {                                                                          \
        cp16(&Ahs[(stage) * 2560 + lrow * 20 + lch], Ah + (size_t)(m0 + lrow) * KU + (ku0) + lch);          \
        cp16(&Ahs[(stage) * 2560 + (lrow + 64) * 20 + lch], Ah + (size_t)(m0 + lrow + 64) * KU + (ku0) + lch); \
        cp16(&Als[(stage) * 2560 + lrow * 20 + lch], Al + (size_t)(m0 + lrow) * KU + (ku0) + lch);          \
        cp16(&Als[(stage) * 2560 + (lrow + 64) * 20 + lch], Al + (size_t)(m0 + lrow + 64) * KU + (ku0) + lch); \
        cp16(&Whs[(stage) * 2560 + lrow * 20 + lch], Wh + (size_t)(n0 + lrow) * KU + (ku0) + lch);          \
        cp16(&Whs[(stage) * 2560 + (lrow + 64) * 20 + lch], Wh + (size_t)(n0 + lrow + 64) * KU + (ku0) + lch); \
        cp16(&Wls[(stage) * 2560 + lrow * 20 + lch], Wl + (size_t)(n0 + lrow) * KU + (ku0) + lch);          \
        cp16(&Wls[(stage) * 2560 + (lrow + 64) * 20 + lch], Wl + (size_t)(n0 + lrow + 64) * KU + (ku0) + lch); \
        CP_COMMIT();                                                              \
    } while (0)

    G_LOAD(0, 0);

    for (int i = 0; i < nk; i++) {
        if (i + 1 < nk) {
            G_LOAD((i + 1) & 1, (i + 1) << 4);
            CP_WAIT(1);
        } else {
            CP_WAIT(0);
        }
        __syncthreads();
        int s = i & 1;
        const unsigned* Ahb = Ahs + s * 2560;
        const unsigned* Alb = Als + s * 2560;
        const unsigned* Whb = Whs + s * 2560;
        const unsigned* Wlb = Wls + s * 2560;
#pragma unroll
        for (int kt = 0; kt < 2; kt++) {
            unsigned ah[2][4], al[2][4];
#pragma unroll
            for (int mi = 0; mi < 2; mi++) {
                int row = wm * 32 + mi * 16 + a_r;
                int col = kt * 8 + a_c;
                ldsm4(ah[mi][0], ah[mi][1], ah[mi][2], ah[mi][3], &Ahb[row * 20 + col]);
                ldsm4(al[mi][0], al[mi][1], al[mi][2], al[mi][3], &Alb[row * 20 + col]);
            }
            unsigned bh[2][4], bl[2][4];
            {
                int row = wn * 64 + b_r;
                int col = kt * 8 + b_c;
                ldsm4(bh[0][0], bh[0][1], bh[0][2], bh[0][3], &Whb[row * 20 + col]);
                ldsm4(bl[0][0], bl[0][1], bl[0][2], bl[0][3], &Wlb[row * 20 + col]);
            }
#pragma unroll
            for (int jp = 0; jp < 4; jp++) {
                int cur = jp & 1;
                if (jp < 3) {
                    int row = wn * 64 + (jp + 1) * 16 + b_r;
                    int col = kt * 8 + b_c;
                    ldsm4(bh[cur ^ 1][0], bh[cur ^ 1][1], bh[cur ^ 1][2], bh[cur ^ 1][3],
                          &Whb[row * 20 + col]);
                    ldsm4(bl[cur ^ 1][0], bl[cur ^ 1][1], bl[cur ^ 1][2], bl[cur ^ 1][3],
                          &Wlb[row * 20 + col]);
                }
#pragma unroll
                for (int mi = 0; mi < 2; mi++) {
                    mma16(acc[mi][jp * 2], ah[mi], bh[cur]);
                    mma16(acc[mi][jp * 2], ah[mi], bl[cur]);
                    mma16(acc[mi][jp * 2], al[mi], bh[cur]);
                    mma16(acc[mi][jp * 2 + 1], ah[mi], bh[cur] + 2);
                    mma16(acc[mi][jp * 2 + 1], ah[mi], bl[cur] + 2);
                    mma16(acc[mi][jp * 2 + 1], al[mi], bh[cur] + 2);
                }
            }
        }
        __syncthreads();
    }
#pragma unroll
    for (int j = 0; j < 8; j++) {
        int col = n0 + wn * 64 + j * 8 + tg * 2;
        float2 bv = *(const float2*)(bias + col);
#pragma unroll
        for (int mi = 0; mi < 2; mi++) {
            int row = m0 + wm * 32 + mi * 16 + g;
            float2 o0 = make_float2(acc[mi][j][0] + bv.x, acc[mi][j][1] + bv.y);
            float2 o1 = make_float2(acc[mi][j][2] + bv.x, acc[mi][j][3] + bv.y);
            *(float2*)(C + (size_t)row * Nn + col) = o0;
            *(float2*)(C + (size_t)(row + 8) * Nn + col) = o1;
        }
    }
}

// ---------------- reorg: normalize q/k, bf16-split+pack; v fp16 pairs ----------
__global__ void reorg_kernel(const float* __restrict__ qe) {
    int wg = blockIdx.x * 8 + (threadIdx.x >> 5);
    int lane = threadIdx.x & 31;
    int h = wg & 15;
    int bn = wg >> 4;
    int b = bn >> 10;
    int n = bn & 1023;
    const float* base = g_qkv + (size_t)bn * (3 * DIMC);
    float q = base[h * HD + lane];
    float k = base[DIMC + h * HD + lane];
    float v = base[2 * DIMC + h * HD + lane];

    float s = q * q;
#pragma unroll
    for (int off = 16; off >= 1; off >>= 1) s += __shfl_xor_sync(0xffffffffu, s, off);
    float qn = q / fmaxf(sqrtf(s), 1e-12f);
    qn = (qn + qe[h * HD + lane]) * g_scale[h];

    s = k * k;
#pragma unroll
    for (int off = 16; off >= 1; off >>= 1) s += __shfl_xor_sync(0xffffffffu, s, off);
    float kn = k / fmaxf(sqrtf(s), 1e-12f);

    __nv_bfloat16 qbh = __float2bfloat16_rn(qn);
    unsigned qhu = (unsigned)__bfloat16_as_ushort(qbh);
    unsigned qlu = (unsigned)__bfloat16_as_ushort(__float2bfloat16_rn(qn - __bfloat162float(qbh)));
    __nv_bfloat16 kbh = __float2bfloat16_rn(kn);
    unsigned khu = (unsigned)__bfloat16_as_ushort(kbh);
    unsigned klu = (unsigned)__bfloat16_as_ushort(__float2bfloat16_rn(kn - __bfloat162float(kbh)));
    unsigned vhu = (unsigned)__half_as_ushort(__float2half_rn(v));

    unsigned qho = __shfl_down_sync(0xffffffffu, qhu, 1);
    unsigned qlo = __shfl_down_sync(0xffffffffu, qlu, 1);
    unsigned kho = __shfl_down_sync(0xffffffffu, khu, 1);
    unsigned klo = __shfl_down_sync(0xffffffffu, klu, 1);
    unsigned vho = __shfl_down_sync(0xffffffffu, vhu, 1);

    size_t rbase = ((size_t)(b * NH + h) * NTOK + n) * (HD / 2);
    if ((lane & 1) == 0) {
        int c = lane >> 1;
        g_qh[rbase + c] = qhu | (qho << 16);
        g_ql[rbase + c] = qlu | (qlo << 16);
        g_kh[rbase + c] = khu | (kho << 16);
        g_kl[rbase + c] = klu | (klo << 16);
        g_vh[rbase + c] = vhu | (vho << 16);
    }
}

// ---------------- attention v13: online softmax + register-P fp16 PV -----------
// grid (B, N/128, H), 256 threads, 128 queries/block, key tiles 64, 1 sync/tile.
// smem: Khs[2][1280], Kls[2][1280], Vhs[2][1280] u32, BBh[2][128*72] half
#define ATTN_SMEM ((3 * 2560 + 9216) * 4)
__global__ __launch_bounds__(256, 2) void attn13_kernel() {
    extern __shared__ unsigned smu[];
    unsigned* Khs = smu;                     // [2][1280]
    unsigned* Kls = smu + 2560;
    unsigned* Vhs = smu + 5120;              // [2][1280]
    __half*  BBh = (__half*)(smu + 7680);    // [2][128*72]

    int b = blockIdx.x, qt = blockIdx.y, h = blockIdx.z;
    int tid = threadIdx.x;
    int w = tid >> 5, lane = tid & 31;
    int g = lane >> 2, tg = lane & 3;

    size_t bh16 = (size_t)(b * NH + h) * NTOK * (HD / 2);
    const unsigned* qhb = g_qh + bh16 + (size_t)qt * 128 * (HD / 2);
    const unsigned* qlb = g_ql + bh16 + (size_t)qt * 128 * (HD / 2);
    const unsigned* khb = g_kh + bh16;
    const unsigned* klb = g_kl + bh16;
    const unsigned* vhb = g_vh + bh16;
    const __half* bbh = g_biash + ((size_t)h * NTOK + qt * 128) * NTOK;

    int krow = tid >> 2, kch = (tid & 3) * 4;
    int brow = tid >> 3, bch = (tid & 7) * 8;
    int b_r = (lane >> 4) * 8 + (lane & 7), b_c = ((lane >> 3) & 1) * 4;   // K ldsm map
    int v_r = ((lane >> 3) & 1) * 8 + (lane & 7), v_c = (lane >> 4) * 4;   // V trans map
#define KVB_LOAD(stage, mt_)                                                      \
    do {                                                                          \
        cp16(&Khs[(stage) * 1280 + krow * 20 + kch], khb + (size_t)((mt_) * 64 + krow) * 16 + kch); \
        cp16(&Kls[(stage) * 1280 + krow * 20 + kch], klb + (size_t)((mt_) * 64 + krow) * 16 + kch); \
        cp16(&Vhs[(stage) * 1280 + krow * 20 + kch], vhb + (size_t)((mt_) * 64 + krow) * 16 + kch); \
        _Pragma("unroll")                                                         \
        for (int p = 0; p < 4; p++) {                                             \
            int row = brow + p * 32;                                              \
            cp16(&BBh[(stage) * 9216 + row * 72 + bch],                           \
                 bbh + (size_t)row * NTOK + (mt_) * 64 + bch);                    \
        }                                                                         \
        CP_COMMIT();                                                              \
    } while (0)

    KVB_LOAD(0, 0);

    unsigned Qh[2][4], Ql[2][4];
    int r = w * 16 + g;
#pragma unroll
    for (int kt = 0; kt < 2; kt++) {
        int c = kt * 8 + tg;
        Qh[kt][0] = qhb[r * 16 + c];           Ql[kt][0] = qlb[r * 16 + c];
        Qh[kt][1] = qhb[(r + 8) * 16 + c];     Ql[kt][1] = qlb[(r + 8) * 16 + c];
        Qh[kt][2] = qhb[r * 16 + c + 4];       Ql[kt][2] = qlb[r * 16 + c + 4];
        Qh[kt][3] = qhb[(r + 8) * 16 + c + 4]; Ql[kt][3] = qlb[(r + 8) * 16 + c + 4];
    }

    float m0 = -INFINITY, m1 = -INFINITY, l0 = 0.0f, l1 = 0.0f;
    float O[4][4];
#pragma unroll
    for (int j = 0; j < 4; j++)
#pragma unroll
        for (int c = 0; c < 4; c++) O[j][c] = 0.0f;

    for (int mt = 0; mt < 16; mt++) {
        int s = mt & 1;
        CP_WAIT(0);
        __syncthreads();   // (A) tile mt visible; all warps done reading stage s^1
        if (mt + 1 < 16) KVB_LOAD(s ^ 1, mt + 1);

        // QK^T: 3xBF16, B fragments double-buffered across (kt,jp)
        float S[8][4];
#pragma unroll
        for (int j = 0; j < 8; j++)
#pragma unroll
            for (int c = 0; c < 4; c++) S[j][c] = 0.0f;
        const unsigned* Khb = Khs + s * 1280;
        const unsigned* Klb = Kls + s * 1280;
        unsigned bh2[2][4], bl2[2][4];
        {
            ldsm4(bh2[0][0], bh2[0][1], bh2[0][2], bh2[0][3], &Khb[b_r * 20 + b_c]);
            ldsm4(bl2[0][0], bl2[0][1], bl2[0][2], bl2[0][3], &Klb[b_r * 20 + b_c]);
        }
#pragma unroll
        for (int u = 0; u < 8; u++) {      // u = kt*4 + jp
            int kt = u >> 2, jp = u & 3;
            int cur = u & 1;
            if (u < 7) {
                int nkt = (u + 1) >> 2, njp = (u + 1) & 3;
                int row = njp * 16 + b_r;
                int col = nkt * 8 + b_c;
                ldsm4(bh2[cur ^ 1][0], bh2[cur ^ 1][1], bh2[cur ^ 1][2], bh2[cur ^ 1][3],
                      &Khb[row * 20 + col]);
                ldsm4(bl2[cur ^ 1][0], bl2[cur ^ 1][1], bl2[cur ^ 1][2], bl2[cur ^ 1][3],
                      &Klb[row * 20 + col]);
            }
            mma16(S[jp * 2], Qh[kt], bh2[cur]);
            mma16(S[jp * 2], Qh[kt], bl2[cur]);
            mma16(S[jp * 2], Ql[kt], bh2[cur]);
            mma16(S[jp * 2 + 1], Qh[kt], bh2[cur] + 2);
            mma16(S[jp * 2 + 1], Qh[kt], bl2[cur] + 2);
            mma16(S[jp * 2 + 1], Ql[kt], bh2[cur] + 2);
        }
        // bias add (fp16 -> fp32)
        const __half* Bb = BBh + s * 9216;
#pragma unroll
        for (int j = 0; j < 8; j++) {
            float2 b0 = __half22float2(*(const __half2*)(Bb + r * 72 + j * 8 + tg * 2));
            float2 b1 = __half22float2(*(const __half2*)(Bb + (r + 8) * 72 + j * 8 + tg * 2));
            S[j][0] += b0.x; S[j][1] += b0.y;
            S[j][2] += b1.x; S[j][3] += b1.y;
        }
        // online softmax (running row max; P in (0,1] -> fp16-safe)
        float mx0 = -INFINITY, mx1 = -INFINITY;
#pragma unroll
        for (int j = 0; j < 8; j++) {
            mx0 = fmaxf(mx0, fmaxf(S[j][0], S[j][1]));
            mx1 = fmaxf(mx1, fmaxf(S[j][2], S[j][3]));
        }
        mx0 = fmaxf(mx0, __shfl_xor_sync(0xffffffffu, mx0, 1));
        mx0 = fmaxf(mx0, __shfl_xor_sync(0xffffffffu, mx0, 2));
        mx1 = fmaxf(mx1, __shfl_xor_sync(0xffffffffu, mx1, 1));
        mx1 = fmaxf(mx1, __shfl_xor_sync(0xffffffffu, mx1, 2));
        float mn0 = fmaxf(m0, mx0), mn1 = fmaxf(m1, mx1);
        float alpha0 = __expf(m0 - mn0), alpha1 = __expf(m1 - mn1);
        m0 = mn0; m1 = mn1;
        float rs0 = 0.0f, rs1 = 0.0f;
#pragma unroll
        for (int j = 0; j < 8; j++) {
            S[j][0] = __expf(S[j][0] - mn0);
            S[j][1] = __expf(S[j][1] - mn0);
            S[j][2] = __expf(S[j][2] - mn1);
            S[j][3] = __expf(S[j][3] - mn1);
            rs0 += S[j][0] + S[j][1];
            rs1 += S[j][2] + S[j][3];
        }
        rs0 += __shfl_xor_sync(0xffffffffu, rs0, 1);
        rs0 += __shfl_xor_sync(0xffffffffu, rs0, 2);
        rs1 += __shfl_xor_sync(0xffffffffu, rs1, 1);
        rs1 += __shfl_xor_sync(0xffffffffu, rs1, 2);
        l0 = l0 * alpha0 + rs0;
        l1 = l1 * alpha1 + rs1;
#pragma unroll
        for (int j = 0; j < 4; j++) {
            O[j][0] *= alpha0; O[j][1] *= alpha0;
            O[j][2] *= alpha1; O[j][3] *= alpha1;
        }
        // pack P fragments to fp16 IN REGISTERS (already the m16n8k16 A layout)
        unsigned Pa[4][4];
#pragma unroll
        for (int kt = 0; kt < 4; kt++) {
            Pa[kt][0] = h2pack(S[2 * kt][0], S[2 * kt][1]);
            Pa[kt][1] = h2pack(S[2 * kt][2], S[2 * kt][3]);
            Pa[kt][2] = h2pack(S[2 * kt + 1][0], S[2 * kt + 1][1]);
            Pa[kt][3] = h2pack(S[2 * kt + 1][2], S[2 * kt + 1][3]);
        }
        // P @ V: fp16 mma, V via trans-ldmatrix (no P smem, no second barrier)
        const unsigned* Vb = Vhs + s * 1280;
#pragma unroll
        for (int kt = 0; kt < 4; kt++) {
            int row = kt * 16 + v_r;
            unsigned bv[8];
            ldsm4t(bv[0], bv[1], bv[2], bv[3], &Vb[row * 20 + v_c]);
            ldsm4t(bv[4], bv[5], bv[6], bv[7], &Vb[row * 20 + 8 + v_c]);
            mma16h(O[0], Pa[kt], bv + 0);
            mma16h(O[1], Pa[kt], bv + 2);
            mma16h(O[2], Pa[kt], bv + 4);
            mma16h(O[3], Pa[kt], bv + 6);
        }
    }
    // epilogue: normalize and pack bf16 hi/lo pairs for proj GEMM
    float inv0 = 1.0f / l0, inv1 = 1.0f / l1;
    int q0r = qt * 128 + w * 16 + g;
    size_t row0 = (size_t)b * NTOK + q0r;
    int colbase = h * 16;
#pragma unroll
    for (int j = 0; j < 4; j++) {
        unsigned hw, lw;
        bf16_split2(O[j][0] * inv0, O[j][1] * inv0, hw, lw);
        g_oh[row0 * 256 + colbase + j * 4 + tg] = hw;
        g_ol[row0 * 256 + colbase + j * 4 + tg] = lw;
        bf16_split2(O[j][2] * inv1, O[j][3] * inv1, hw, lw);
        g_oh[(row0 + 8) * 256 + colbase + j * 4 + tg] = hw;
        g_ol[(row0 + 8) * 256 + colbase + j * 4 + tg] = lw;
    }
}

// ---------------- launcher ---------------------------------------------------
extern "C" void kernel_launch(void* const* d_in, const int* in_sizes, int n_in,
                              void* d_out, int out_size) {
    const float* x      = (const float*)d_in[0];
    const int*   rpi    = (const int*)d_in[3];
    const float* table  = (const float*)d_in[4];
    const float* qkv_w  = (const float*)d_in[5];
    const float* qkv_b  = (const float*)d_in[6];
    const float* proj_w = (const float*)d_in[7];
    const float* proj_b = (const float*)d_in[8];
    const float* temp   = (const float*)d_in[9];
    const float* qe     = (const float*)d_in[10];
    const float* fc1w   = (const float*)d_in[11];
    const float* fc1b   = (const float*)d_in[12];
    const float* fc2w   = (const float*)d_in[13];
    const float* fc2b   = (const float*)d_in[14];
    float* out = (float*)d_out;

    float* p_qkv;  cudaGetSymbolAddress((void**)&p_qkv,  g_qkv);
    unsigned* p_wh; cudaGetSymbolAddress((void**)&p_wh, g_wh);
    unsigned* p_wl; cudaGetSymbolAddress((void**)&p_wl, g_wl);
    unsigned* p_xh; cudaGetSymbolAddress((void**)&p_xh, g_xh);
    unsigned* p_xl; cudaGetSymbolAddress((void**)&p_xl, g_xl);
    unsigned* p_oh; cudaGetSymbolAddress((void**)&p_oh, g_oh);
    unsigned* p_ol; cudaGetSymbolAddress((void**)&p_ol, g_ol);

    static int attr_set = 0;
    if (!attr_set) {
        cudaFuncSetAttribute(attn13_kernel, cudaFuncAttributeMaxDynamicSharedMemorySize,
                             ATTN_SMEM);
        cudaFuncSetAttribute(gemm3b, cudaFuncAttributeMaxDynamicSharedMemorySize,
                             GEMM_SMEM);
        attr_set = 1;
    }

    split_kernel<<<(NW2 + NX2) / 256, 256>>>(qkv_w, proj_w, x);
    cpb_kernel<<<TABLE_SZ, 512>>>(table, fc1w, fc1b, fc2w, fc2b, temp);
    bias_kernel<<<NTOK, 256>>>(rpi);
    {
        dim3 grid(3 * DIMC / 128, BATCH * NTOK / 128);
        gemm3b<<<grid, 256, GEMM_SMEM>>>(p_xh, p_xl, p_wh, p_wl, qkv_b, p_qkv,
                                         BATCH * NTOK, 3 * DIMC, DIMC);
    }
    reorg_kernel<<<BATCH * NTOK * NH / 8, 256>>>(qe);
    {
        dim3 grid(BATCH, NTOK / 128, NH);
        attn13_kernel<<<grid, 256, ATTN_SMEM>>>();
    }
    {
        dim3 grid(DIMC / 128, BATCH * NTOK / 128);
        gemm3b<<<grid, 256, GEMM_SMEM>>>(p_oh, p_ol, p_wh + 3 * DIMC * DIMC / 2,
                                         p_wl + 3 * DIMC * DIMC / 2, proj_b, out,
                                         BATCH * NTOK, DIMC, DIMC);
    }
}

// round 14
// speedup vs baseline: 1.2867x; 1.0094x over previous
#include <cuda_runtime.h>
#include <cuda_bf16.h>
#include <cuda_fp16.h>
#include <math.h>

// Problem constants
#define BATCH 8
#define NTOK 1024
#define DIMC 512
#define NH 16
#define HD 32
#define TABLE_SZ 3969
#define SEQ_SCALE 6.93147180559945309f  // ln(1024)

// ---------------- scratch (device globals; no allocation allowed) -------------
__device__ float g_t[TABLE_SZ * NH];
__device__ __half g_biash[NH * NTOK * NTOK];            // [h][n][m] 32MB fp16
__device__ float g_qkv[BATCH * NTOK * 3 * DIMC];        // 50MB
__device__ unsigned g_qh[BATCH * NH * NTOK * HD / 2];   // q hi, packed bf16 pairs
__device__ unsigned g_ql[BATCH * NH * NTOK * HD / 2];   // q lo
__device__ unsigned g_kh[BATCH * NH * NTOK * HD / 2];   // k hi
__device__ unsigned g_kl[BATCH * NH * NTOK * HD / 2];   // k lo
__device__ unsigned g_vh[BATCH * NH * NTOK * HD / 2];   // v fp16 pairs [key][d]
__device__ unsigned g_oh[BATCH * NTOK * DIMC / 2];      // attn out hi (bf16 pairs)
__device__ unsigned g_ol[BATCH * NTOK * DIMC / 2];      // attn out lo
__device__ unsigned g_xh[BATCH * NTOK * DIMC / 2];      // x hi
__device__ unsigned g_xl[BATCH * NTOK * DIMC / 2];      // x lo
__device__ unsigned g_wh[(3 * DIMC + DIMC) * DIMC / 2]; // W hi (qkv then proj)
__device__ unsigned g_wl[(3 * DIMC + DIMC) * DIMC / 2]; // W lo

// ---------------- helpers -----------------------------------------------------
__device__ __forceinline__ void bf16_split2(float e, float o, unsigned& hi, unsigned& lo) {
    __nv_bfloat162 h2 = __floats2bfloat162_rn(e, o);
    hi = *(unsigned*)&h2;
    float re = e - __bfloat162float(h2.x);
    float ro = o - __bfloat162float(h2.y);
    __nv_bfloat162 l2 = __floats2bfloat162_rn(re, ro);
    lo = *(unsigned*)&l2;
}
__device__ __forceinline__ unsigned h2pack(float e, float o) {
    __half2 h = __floats2half2_rn(e, o);
    return *(unsigned*)&h;
}
__device__ __forceinline__ void mma16(float* c, const unsigned* a, const unsigned* b) {
    asm volatile("mma.sync.aligned.m16n8k16.row.col.f32.bf16.bf16.f32 "
                 "{%0,%1,%2,%3}, {%4,%5,%6,%7}, {%8,%9}, {%0,%1,%2,%3};"
                 : "+f"(c[0]), "+f"(c[1]), "+f"(c[2]), "+f"(c[3])
                 : "r"(a[0]), "r"(a[1]), "r"(a[2]), "r"(a[3]),
                   "r"(b[0]), "r"(b[1]));
}
__device__ __forceinline__ void mma16h(float* c, const unsigned* a, const unsigned* b) {
    asm volatile("mma.sync.aligned.m16n8k16.row.col.f32.f16.f16.f32 "
                 "{%0,%1,%2,%3}, {%4,%5,%6,%7}, {%8,%9}, {%0,%1,%2,%3};"
                 : "+f"(c[0]), "+f"(c[1]), "+f"(c[2]), "+f"(c[3])
                 : "r"(a[0]), "r"(a[1]), "r"(a[2]), "r"(a[3]),
                   "r"(b[0]), "r"(b[1]));
}
__device__ __forceinline__ void ldsm4(unsigned& r0, unsigned& r1, unsigned& r2,
                                      unsigned& r3, const void* p) {
    unsigned a = (unsigned)__cvta_generic_to_shared(p);
    asm volatile("ldmatrix.sync.aligned.m8n8.x4.shared.b16 {%0,%1,%2,%3}, [%4];"
                 : "=r"(r0), "=r"(r1), "=r"(r2), "=r"(r3) : "r"(a));
}
__device__ __forceinline__ void ldsm4t(unsigned& r0, unsigned& r1, unsigned& r2,
                                       unsigned& r3, const void* p) {
    unsigned a = (unsigned)__cvta_generic_to_shared(p);
    asm volatile("ldmatrix.sync.aligned.m8n8.x4.trans.shared.b16 {%0,%1,%2,%3}, [%4];"
                 : "=r"(r0), "=r"(r1), "=r"(r2), "=r"(r3) : "r"(a));
}
__device__ __forceinline__ void cp16(void* sdst, const void* gsrc) {
    unsigned u = (unsigned)__cvta_generic_to_shared(sdst);
    asm volatile("cp.async.ca.shared.global [%0], [%1], 16;" :: "r"(u), "l"(gsrc));
}
#define CP_COMMIT() asm volatile("cp.async.commit_group;")
#define CP_WAIT(n)  asm volatile("cp.async.wait_group %0;" :: "n"(n))

// ---------------- fused split: weights + x (bf16 hi/lo pairs) ------------------
#define NW2 (4 * DIMC * DIMC / 2)
#define NX2 (BATCH * NTOK * DIMC / 2)
__global__ void split_kernel(const float* __restrict__ qkvw,
                             const float* __restrict__ projw,
                             const float* __restrict__ x) {
    int i = blockIdx.x * 256 + threadIdx.x;
    unsigned h, l;
    if (i < NW2) {
        int nq2 = 3 * DIMC * DIMC / 2;
        float2 v = (i < nq2) ? ((const float2*)qkvw)[i] : ((const float2*)projw)[i - nq2];
        bf16_split2(v.x, v.y, h, l);
        g_wh[i] = h; g_wl[i] = l;
    } else {
        int j = i - NW2;
        float2 v = ((const float2*)x)[j];
        bf16_split2(v.x, v.y, h, l);
        g_xh[j] = h; g_xl[j] = l;
    }
}

// ---------------- CPB MLP t[r][h] ---------------------------------------------
__global__ void cpb_kernel(const float* __restrict__ table,
                           const float* __restrict__ fc1w,
                           const float* __restrict__ fc1b,
                           const float* __restrict__ fc2w,
                           const float* __restrict__ fc2b) {
    __shared__ float hid[512];
    int r = blockIdx.x;
    int j = threadIdx.x;
    float c0 = table[r * 2 + 0];
    float c1 = table[r * 2 + 1];
    float hv = c0 * fc1w[j * 2 + 0] + c1 * fc1w[j * 2 + 1] + fc1b[j];
    hid[j] = fmaxf(hv, 0.0f);
    __syncthreads();
    int w = j >> 5;
    int lane = j & 31;
    float acc = 0.0f;
#pragma unroll
    for (int kk = lane; kk < 512; kk += 32) acc += hid[kk] * fc2w[w * 512 + kk];
#pragma unroll
    for (int off = 16; off >= 1; off >>= 1) acc += __shfl_xor_sync(0xffffffffu, acc, off);
    if (lane == 0) g_t[r * NH + w] = acc + fc2b[w];
}

// ---------------- bias gather  biash[h][n][m] = half(t[rpi[n][m]][h]) ---------
__global__ void bias_kernel(const int* __restrict__ rpi) {
    int n = blockIdx.x;
    for (int m = threadIdx.x; m < NTOK; m += blockDim.x) {
        int idx = rpi[n * NTOK + m];
        const float4* tp = (const float4*)(g_t + idx * NH);
        float4 t0 = tp[0], t1 = tp[1], t2 = tp[2], t3 = tp[3];
        float v[16] = {t0.x, t0.y, t0.z, t0.w, t1.x, t1.y, t1.z, t1.w,
                       t2.x, t2.y, t2.z, t2.w, t3.x, t3.y, t3.z, t3.w};
#pragma unroll
        for (int h = 0; h < NH; h++)
            g_biash[((size_t)h * NTOK + n) * NTOK + m] = __float2half(v[h]);
    }
}

// ---------------- 3xBF16 GEMM, cp.async 2-stage, pipelined ldmatrix ------------
#define GEMM_SMEM (4 * 2 * 128 * 20 * 4)
__global__ __launch_bounds__(256, 2) void gemm3b(const unsigned* __restrict__ Ah,
                                                 const unsigned* __restrict__ Al,
                                                 const unsigned* __restrict__ Wh,
                                                 const unsigned* __restrict__ Wl,
                                                 const float* __restrict__ bias,
                                                 float* __restrict__ C,
                                                 int M, int Nn, int K) {
    extern __shared__ unsigned smg[];
    unsigned* Ahs = smg;               // [2][2560]
    unsigned* Als = smg + 2 * 2560;
    unsigned* Whs = smg + 4 * 2560;
    unsigned* Wls = smg + 6 * 2560;

    int tid = threadIdx.x;
    int wid = tid >> 5, lane = tid & 31;
    int g = lane >> 2, tg = lane & 3;
    int wm = wid & 3, wn = wid >> 2;
    int m0 = blockIdx.y * 128, n0 = blockIdx.x * 128;
    int KU = K >> 1;

    int lrow = tid >> 2, lch = (tid & 3) * 4;
    int a_r = (lane & 15), a_c = (lane >> 4) * 4;
    int b_r = (lane >> 4) * 8 + (lane & 7), b_c = ((lane >> 3) & 1) * 4;

    float acc[2][8][4];
#pragma unroll
    for (int mi = 0; mi < 2; mi++)
#pragma unroll
        for (int j = 0; j < 8; j++)
#pragma unroll
            for (int c = 0; c < 4; c++) acc[mi][j][c] = 0.0f;

    int nk = K >> 5;
#define G_LOAD(stage, ku0)                                                        \
    do {                                                                          \
        cp16(&Ahs[(stage) * 2560 + lrow * 20 + lch], Ah + (size_t)(m0 + lrow) * KU + (ku0) + lch);          \
        cp16(&Ahs[(stage) * 2560 + (lrow + 64) * 20 + lch], Ah + (size_t)(m0 + lrow + 64) * KU + (ku0) + lch); \
        cp16(&Als[(stage) * 2560 + lrow * 20 + lch], Al + (size_t)(m0 + lrow) * KU + (ku0) + lch);          \
        cp16(&Als[(stage) * 2560 + (lrow + 64) * 20 + lch], Al + (size_t)(m0 + lrow + 64) * KU + (ku0) + lch); \
        cp16(&Whs[(stage) * 2560 + lrow * 20 + lch], Wh + (size_t)(n0 + lrow) * KU + (ku0) + lch);          \
        cp16(&Whs[(stage) * 2560 + (lrow + 64) * 20 + lch], Wh + (size_t)(n0 + lrow + 64) * KU + (ku0) + lch); \
        cp16(&Wls[(stage) * 2560 + lrow * 20 + lch], Wl + (size_t)(n0 + lrow) * KU + (ku0) + lch);          \
        cp16(&Wls[(stage) * 2560 + (lrow + 64) * 20 + lch], Wl + (size_t)(n0 + lrow + 64) * KU + (ku0) + lch); \
        CP_COMMIT();                                                              \
    } while (0)

    G_LOAD(0, 0);

    for (int i = 0; i < nk; i++) {
        if (i + 1 < nk) {
            G_LOAD((i + 1) & 1, (i + 1) << 4);
            CP_WAIT(1);
        } else {
            CP_WAIT(0);
        }
        __syncthreads();
        int s = i & 1;
        const unsigned* Ahb = Ahs + s * 2560;
        const unsigned* Alb = Als + s * 2560;
        const unsigned* Whb = Whs + s * 2560;
        const unsigned* Wlb = Wls + s * 2560;
#pragma unroll
        for (int kt = 0; kt < 2; kt++) {
            unsigned ah[2][4], al[2][4];
#pragma unroll
            for (int mi = 0; mi < 2; mi++) {
                int row = wm * 32 + mi * 16 + a_r;
                int col = kt * 8 + a_c;
                ldsm4(ah[mi][0], ah[mi][1], ah[mi][2], ah[mi][3], &Ahb[row * 20 + col]);
                ldsm4(al[mi][0], al[mi][1], al[mi][2], al[mi][3], &Alb[row * 20 + col]);
            }
            unsigned bh[2][4], bl[2][4];
            {
                int row = wn * 64 + b_r;
                int col = kt * 8 + b_c;
                ldsm4(bh[0][0], bh[0][1], bh[0][2], bh[0][3], &Whb[row * 20 + col]);
                ldsm4(bl[0][0], bl[0][1], bl[0][2], bl[0][3], &Wlb[row * 20 + col]);
            }
#pragma unroll
            for (int jp = 0; jp < 4; jp++) {
                int cur = jp & 1;
                if (jp < 3) {
                    int row = wn * 64 + (jp + 1) * 16 + b_r;
                    int col = kt * 8 + b_c;
                    ldsm4(bh[cur ^ 1][0], bh[cur ^ 1][1], bh[cur ^ 1][2], bh[cur ^ 1][3],
                          &Whb[row * 20 + col]);
                    ldsm4(bl[cur ^ 1][0], bl[cur ^ 1][1], bl[cur ^ 1][2], bl[cur ^ 1][3],
                          &Wlb[row * 20 + col]);
                }
#pragma unroll
                for (int mi = 0; mi < 2; mi++) {
                    mma16(acc[mi][jp * 2], ah[mi], bh[cur]);
                    mma16(acc[mi][jp * 2], ah[mi], bl[cur]);
                    mma16(acc[mi][jp * 2], al[mi], bh[cur]);
                    mma16(acc[mi][jp * 2 + 1], ah[mi], bh[cur] + 2);
                    mma16(acc[mi][jp * 2 + 1], ah[mi], bl[cur] + 2);
                    mma16(acc[mi][jp * 2 + 1], al[mi], bh[cur] + 2);
                }
            }
        }
        __syncthreads();
    }
#pragma unroll
    for (int j = 0; j < 8; j++) {
        int col = n0 + wn * 64 + j * 8 + tg * 2;
        float2 bv = *(const float2*)(bias + col);
#pragma unroll
        for (int mi = 0; mi < 2; mi++) {
            int row = m0 + wm * 32 + mi * 16 + g;
            float2 o0 = make_float2(acc[mi][j][0] + bv.x, acc[mi][j][1] + bv.y);
            float2 o1 = make_float2(acc[mi][j][2] + bv.x, acc[mi][j][3] + bv.y);
            *(float2*)(C + (size_t)row * Nn + col) = o0;
            *(float2*)(C + (size_t)(row + 8) * Nn + col) = o1;
        }
    }
}

// ---------------- reorg: normalize q/k, bf16-split+pack; v fp16 pairs ----------
// scale computed locally (removes cross-stream dependency on cpb)
__global__ void reorg_kernel(const float* __restrict__ qe,
                             const float* __restrict__ temp) {
    int wg = blockIdx.x * 8 + (threadIdx.x >> 5);
    int lane = threadIdx.x & 31;
    int h = wg & 15;
    int bn = wg >> 4;
    int b = bn >> 10;
    int n = bn & 1023;
    const float* base = g_qkv + (size_t)bn * (3 * DIMC);
    float q = base[h * HD + lane];
    float k = base[DIMC + h * HD + lane];
    float v = base[2 * DIMC + h * HD + lane];

    float t = temp[h];
    float scale = ((t > 20.0f) ? t : log1pf(expf(t))) * SEQ_SCALE;

    float s = q * q;
#pragma unroll
    for (int off = 16; off >= 1; off >>= 1) s += __shfl_xor_sync(0xffffffffu, s, off);
    float qn = q / fmaxf(sqrtf(s), 1e-12f);
    qn = (qn + qe[h * HD + lane]) * scale;

    s = k * k;
#pragma unroll
    for (int off = 16; off >= 1; off >>= 1) s += __shfl_xor_sync(0xffffffffu, s, off);
    float kn = k / fmaxf(sqrtf(s), 1e-12f);

    __nv_bfloat16 qbh = __float2bfloat16_rn(qn);
    unsigned qhu = (unsigned)__bfloat16_as_ushort(qbh);
    unsigned qlu = (unsigned)__bfloat16_as_ushort(__float2bfloat16_rn(qn - __bfloat162float(qbh)));
    __nv_bfloat16 kbh = __float2bfloat16_rn(kn);
    unsigned khu = (unsigned)__bfloat16_as_ushort(kbh);
    unsigned klu = (unsigned)__bfloat16_as_ushort(__float2bfloat16_rn(kn - __bfloat162float(kbh)));
    unsigned vhu = (unsigned)__half_as_ushort(__float2half_rn(v));

    unsigned qho = __shfl_down_sync(0xffffffffu, qhu, 1);
    unsigned qlo = __shfl_down_sync(0xffffffffu, qlu, 1);
    unsigned kho = __shfl_down_sync(0xffffffffu, khu, 1);
    unsigned klo = __shfl_down_sync(0xffffffffu, klu, 1);
    unsigned vho = __shfl_down_sync(0xffffffffu, vhu, 1);

    size_t rbase = ((size_t)(b * NH + h) * NTOK + n) * (HD / 2);
    if ((lane & 1) == 0) {
        int c = lane >> 1;
        g_qh[rbase + c] = qhu | (qho << 16);
        g_ql[rbase + c] = qlu | (qlo << 16);
        g_kh[rbase + c] = khu | (kho << 16);
        g_kl[rbase + c] = klu | (klo << 16);
        g_vh[rbase + c] = vhu | (vho << 16);
    }
}

// ---------------- attention v13: online softmax + register-P fp16 PV -----------
#define ATTN_SMEM ((3 * 2560 + 9216) * 4)
__global__ __launch_bounds__(256, 2) void attn13_kernel() {
    extern __shared__ unsigned smu[];
    unsigned* Khs = smu;                     // [2][1280]
    unsigned* Kls = smu + 2560;
    unsigned* Vhs = smu + 5120;              // [2][1280]
    __half*  BBh = (__half*)(smu + 7680);    // [2][128*72]

    int b = blockIdx.x, qt = blockIdx.y, h = blockIdx.z;
    int tid = threadIdx.x;
    int w = tid >> 5, lane = tid & 31;
    int g = lane >> 2, tg = lane & 3;

    size_t bh16 = (size_t)(b * NH + h) * NTOK * (HD / 2);
    const unsigned* qhb = g_qh + bh16 + (size_t)qt * 128 * (HD / 2);
    const unsigned* qlb = g_ql + bh16 + (size_t)qt * 128 * (HD / 2);
    const unsigned* khb = g_kh + bh16;
    const unsigned* klb = g_kl + bh16;
    const unsigned* vhb = g_vh + bh16;
    const __half* bbh = g_biash + ((size_t)h * NTOK + qt * 128) * NTOK;

    int krow = tid >> 2, kch = (tid & 3) * 4;
    int brow = tid >> 3, bch = (tid & 7) * 8;
    int b_r = (lane >> 4) * 8 + (lane & 7), b_c = ((lane >> 3) & 1) * 4;
    int v_r = ((lane >> 3) & 1) * 8 + (lane & 7), v_c = (lane >> 4) * 4;
#define KVB_LOAD(stage, mt_)                                                      \
    do {                                                                          \
        cp16(&Khs[(stage) * 1280 + krow * 20 + kch], khb + (size_t)((mt_) * 64 + krow) * 16 + kch); \
        cp16(&Kls[(stage) * 1280 + krow * 20 + kch], klb + (size_t)((mt_) * 64 + krow) * 16 + kch); \
        cp16(&Vhs[(stage) * 1280 + krow * 20 + kch], vhb + (size_t)((mt_) * 64 + krow) * 16 + kch); \
        _Pragma("unroll")                                                         \
        for (int p = 0; p < 4; p++) {                                             \
            int row = brow + p * 32;                                              \
            cp16(&BBh[(stage) * 9216 + row * 72 + bch],                           \
                 bbh + (size_t)row * NTOK + (mt_) * 64 + bch);                    \
        }                                                                         \
        CP_COMMIT();                                                              \
    } while (0)

    KVB_LOAD(0, 0);

    unsigned Qh[2][4], Ql[2][4];
    int r = w * 16 + g;
#pragma unroll
    for (int kt = 0; kt < 2; kt++) {
        int c = kt * 8 + tg;
        Qh[kt][0] = qhb[r * 16 + c];           Ql[kt][0] = qlb[r * 16 + c];
        Qh[kt][1] = qhb[(r + 8) * 16 + c];     Ql[kt][1] = qlb[(r + 8) * 16 + c];
        Qh[kt][2] = qhb[r * 16 + c + 4];       Ql[kt][2] = qlb[r * 16 + c + 4];
        Qh[kt][3] = qhb[(r + 8) * 16 + c + 4]; Ql[kt][3] = qlb[(r + 8) * 16 + c + 4];
    }

    float m0 = -INFINITY, m1 = -INFINITY, l0 = 0.0f, l1 = 0.0f;
    float O[4][4];
#pragma unroll
    for (int j = 0; j < 4; j++)
#pragma unroll
        for (int c = 0; c < 4; c++) O[j][c] = 0.0f;

    for (int mt = 0; mt < 16; mt++) {
        int s = mt & 1;
        CP_WAIT(0);
        __syncthreads();   // (A) tile mt visible; all warps done reading stage s^1
        if (mt + 1 < 16) KVB_LOAD(s ^ 1, mt + 1);

        float S[8][4];
#pragma unroll
        for (int j = 0; j < 8; j++)
#pragma unroll
            for (int c = 0; c < 4; c++) S[j][c] = 0.0f;
        const unsigned* Khb = Khs + s * 1280;
        const unsigned* Klb = Kls + s * 1280;
        unsigned bh2[2][4], bl2[2][4];
        {
            ldsm4(bh2[0][0], bh2[0][1], bh2[0][2], bh2[0][3], &Khb[b_r * 20 + b_c]);
            ldsm4(bl2[0][0], bl2[0][1], bl2[0][2], bl2[0][3], &Klb[b_r * 20 + b_c]);
        }
#pragma unroll
        for (int u = 0; u < 8; u++) {
            int kt = u >> 2, jp = u & 3;
            int cur = u & 1;
            if (u < 7) {
                int nkt = (u + 1) >> 2, njp = (u + 1) & 3;
                int row = njp * 16 + b_r;
                int col = nkt * 8 + b_c;
                ldsm4(bh2[cur ^ 1][0], bh2[cur ^ 1][1], bh2[cur ^ 1][2], bh2[cur ^ 1][3],
                      &Khb[row * 20 + col]);
                ldsm4(bl2[cur ^ 1][0], bl2[cur ^ 1][1], bl2[cur ^ 1][2], bl2[cur ^ 1][3],
                      &Klb[row * 20 + col]);
            }
            mma16(S[jp * 2], Qh[kt], bh2[cur]);
            mma16(S[jp * 2], Qh[kt], bl2[cur]);
            mma16(S[jp * 2], Ql[kt], bh2[cur]);
            mma16(S[jp * 2 + 1], Qh[kt], bh2[cur] + 2);
            mma16(S[jp * 2 + 1], Qh[kt], bl2[cur] + 2);
            mma16(S[jp * 2 + 1], Ql[kt], bh2[cur] + 2);
        }
        const __half* Bb = BBh + s * 9216;
#pragma unroll
        for (int j = 0; j < 8; j++) {
            float2 b0 = __half22float2(*(const __half2*)(Bb + r * 72 + j * 8 + tg * 2));
            float2 b1 = __half22float2(*(const __half2*)(Bb + (r + 8) * 72 + j * 8 + tg * 2));
            S[j][0] += b0.x; S[j][1] += b0.y;
            S[j][2] += b1.x; S[j][3] += b1.y;
        }
        float mx0 = -INFINITY, mx1 = -INFINITY;
#pragma unroll
        for (int j = 0; j < 8; j++) {
            mx0 = fmaxf(mx0, fmaxf(S[j][0], S[j][1]));
            mx1 = fmaxf(mx1, fmaxf(S[j][2], S[j][3]));
        }
        mx0 = fmaxf(mx0, __shfl_xor_sync(0xffffffffu, mx0, 1));
        mx0 = fmaxf(mx0, __shfl_xor_sync(0xffffffffu, mx0, 2));
        mx1 = fmaxf(mx1, __shfl_xor_sync(0xffffffffu, mx1, 1));
        mx1 = fmaxf(mx1, __shfl_xor_sync(0xffffffffu, mx1, 2));
        float mn0 = fmaxf(m0, mx0), mn1 = fmaxf(m1, mx1);
        float alpha0 = __expf(m0 - mn0), alpha1 = __expf(m1 - mn1);
        m0 = mn0; m1 = mn1;
        float rs0 = 0.0f, rs1 = 0.0f;
#pragma unroll
        for (int j = 0; j < 8; j++) {
            S[j][0] = __expf(S[j][0] - mn0);
            S[j][1] = __expf(S[j][1] - mn0);
            S[j][2] = __expf(S[j][2] - mn1);
            S[j][3] = __expf(S[j][3] - mn1);
            rs0 += S[j][0] + S[j][1];
            rs1 += S[j][2] + S[j][3];
        }
        rs0 += __shfl_xor_sync(0xffffffffu, rs0, 1);
        rs0 += __shfl_xor_sync(0xffffffffu, rs0, 2);
        rs1 += __shfl_xor_sync(0xffffffffu, rs1, 1);
        rs1 += __shfl_xor_sync(0xffffffffu, rs1, 2);
        l0 = l0 * alpha0 + rs0;
        l1 = l1 * alpha1 + rs1;
#pragma unroll
        for (int j = 0; j < 4; j++) {
            O[j][0] *= alpha0; O[j][1] *= alpha0;
            O[j][2] *= alpha1; O[j][3] *= alpha1;
        }
        unsigned Pa[4][4];
#pragma unroll
        for (int kt = 0; kt < 4; kt++) {
            Pa[kt][0] = h2pack(S[2 * kt][0], S[2 * kt][1]);
            Pa[kt][1] = h2pack(S[2 * kt][2], S[2 * kt][3]);
            Pa[kt][2] = h2pack(S[2 * kt + 1][0], S[2 * kt + 1][1]);
            Pa[kt][3] = h2pack(S[2 * kt + 1][2], S[2 * kt + 1][3]);
        }
        const unsigned* Vb = Vhs + s * 1280;
#pragma unroll
        for (int kt = 0; kt < 4; kt++) {
            int row = kt * 16 + v_r;
            unsigned bv[8];
            ldsm4t(bv[0], bv[1], bv[2], bv[3], &Vb[row * 20 + v_c]);
            ldsm4t(bv[4], bv[5], bv[6], bv[7], &Vb[row * 20 + 8 + v_c]);
            mma16h(O[0], Pa[kt], bv + 0);
            mma16h(O[1], Pa[kt], bv + 2);
            mma16h(O[2], Pa[kt], bv + 4);
            mma16h(O[3], Pa[kt], bv + 6);
        }
    }
    float inv0 = 1.0f / l0, inv1 = 1.0f / l1;
    int q0r = qt * 128 + w * 16 + g;
    size_t row0 = (size_t)b * NTOK + q0r;
    int colbase = h * 16;
#pragma unroll
    for (int j = 0; j < 4; j++) {
        unsigned hw, lw;
        bf16_split2(O[j][0] * inv0, O[j][1] * inv0, hw, lw);
        g_oh[row0 * 256 + colbase + j * 4 + tg] = hw;
        g_ol[row0 * 256 + colbase + j * 4 + tg] = lw;
        bf16_split2(O[j][2] * inv1, O[j][3] * inv1, hw, lw);
        g_oh[(row0 + 8) * 256 + colbase + j * 4 + tg] = hw;
        g_ol[(row0 + 8) * 256 + colbase + j * 4 + tg] = lw;
    }
}

// ---------------- launcher: fork-join streams under graph capture --------------
extern "C" void kernel_launch(void* const* d_in, const int* in_sizes, int n_in,
                              void* d_out, int out_size) {
    const float* x      = (const float*)d_in[0];
    const int*   rpi    = (const int*)d_in[3];
    const float* table  = (const float*)d_in[4];
    const float* qkv_w  = (const float*)d_in[5];
    const float* qkv_b  = (const float*)d_in[6];
    const float* proj_w = (const float*)d_in[7];
    const float* proj_b = (const float*)d_in[8];
    const float* temp   = (const float*)d_in[9];
    const float* qe     = (const float*)d_in[10];
    const float* fc1w   = (const float*)d_in[11];
    const float* fc1b   = (const float*)d_in[12];
    const float* fc2w   = (const float*)d_in[13];
    const float* fc2b   = (const float*)d_in[14];
    float* out = (float*)d_out;

    float* p_qkv;  cudaGetSymbolAddress((void**)&p_qkv,  g_qkv);
    unsigned* p_wh; cudaGetSymbolAddress((void**)&p_wh, g_wh);
    unsigned* p_wl; cudaGetSymbolAddress((void**)&p_wl, g_wl);
    unsigned* p_xh; cudaGetSymbolAddress((void**)&p_xh, g_xh);
    unsigned* p_xl; cudaGetSymbolAddress((void**)&p_xl, g_xl);
    unsigned* p_oh; cudaGetSymbolAddress((void**)&p_oh, g_oh);
    unsigned* p_ol; cudaGetSymbolAddress((void**)&p_ol, g_ol);

    static int attr_set = 0;
    static cudaStream_t s2;
    static cudaEvent_t e_fork, e_join;
    if (!attr_set) {
        cudaFuncSetAttribute(attn13_kernel, cudaFuncAttributeMaxDynamicSharedMemorySize,
                             ATTN_SMEM);
        cudaFuncSetAttribute(gemm3b, cudaFuncAttributeMaxDynamicSharedMemorySize,
                             GEMM_SMEM);
        cudaStreamCreateWithFlags(&s2, cudaStreamNonBlocking);
        cudaEventCreateWithFlags(&e_fork, cudaEventDisableTiming);
        cudaEventCreateWithFlags(&e_join, cudaEventDisableTiming);
        attr_set = 1;
    }

    // fork: cpb -> bias on side stream (independent of main chain)
    cudaEventRecord(e_fork, 0);
    cudaStreamWaitEvent(s2, e_fork, 0);
    cpb_kernel<<<TABLE_SZ, 512, 0, s2>>>(table, fc1w, fc1b, fc2w, fc2b);
    bias_kernel<<<NTOK, 256, 0, s2>>>(rpi);
    cudaEventRecord(e_join, s2);

    // main chain: split -> qkv gemm -> reorg
    split_kernel<<<(NW2 + NX2) / 256, 256>>>(qkv_w, proj_w, x);
    {
        dim3 grid(3 * DIMC / 128, BATCH * NTOK / 128);
        gemm3b<<<grid, 256, GEMM_SMEM>>>(p_xh, p_xl, p_wh, p_wl, qkv_b, p_qkv,
                                         BATCH * NTOK, 3 * DIMC, DIMC);
    }
    reorg_kernel<<<BATCH * NTOK * NH / 8, 256>>>(qe, temp);

    // join: attention needs bias
    cudaStreamWaitEvent(0, e_join, 0);
    {
        dim3 grid(BATCH, NTOK / 128, NH);
        attn13_kernel<<<grid, 256, ATTN_SMEM>>>();
    }
    {
        dim3 grid(DIMC / 128, BATCH * NTOK / 128);
        gemm3b<<<grid, 256, GEMM_SMEM>>>(p_oh, p_ol, p_wh + 3 * DIMC * DIMC / 2,
                                         p_wl + 3 * DIMC * DIMC / 2, proj_b, out,
                                         BATCH * NTOK, DIMC, DIMC);
    }
}

// round 15
// speedup vs baseline: 1.3184x; 1.0246x over previous
#include <cuda_runtime.h>
#include <cuda_bf16.h>
#include <cuda_fp16.h>
#include <math.h>

// Problem constants
#define BATCH 8
#define NTOK 1024
#define DIMC 512
#define NH 16
#define HD 32
#define TABLE_SZ 3969
#define SEQ_SCALE 6.93147180559945309f  // ln(1024)

// ---------------- scratch (device globals; no allocation allowed) -------------
__device__ float g_t[TABLE_SZ * NH];
__device__ __half g_biash[NH * NTOK * NTOK];            // [h][n][m] 32MB fp16
__device__ unsigned g_qh[BATCH * NH * NTOK * HD / 2];   // q hi, packed bf16 pairs
__device__ unsigned g_ql[BATCH * NH * NTOK * HD / 2];   // q lo
__device__ unsigned g_kh[BATCH * NH * NTOK * HD / 2];   // k hi
__device__ unsigned g_kl[BATCH * NH * NTOK * HD / 2];   // k lo
__device__ unsigned g_vh[BATCH * NH * NTOK * HD / 2];   // v fp16 pairs [key][d]
__device__ unsigned g_oh[BATCH * NTOK * DIMC / 2];      // attn out hi (bf16 pairs)
__device__ unsigned g_ol[BATCH * NTOK * DIMC / 2];      // attn out lo
__device__ unsigned g_xh[BATCH * NTOK * DIMC / 2];      // x hi
__device__ unsigned g_xl[BATCH * NTOK * DIMC / 2];      // x lo
__device__ unsigned g_wh[(3 * DIMC + DIMC) * DIMC / 2]; // W hi (qkv then proj)
__device__ unsigned g_wl[(3 * DIMC + DIMC) * DIMC / 2]; // W lo

// ---------------- helpers -----------------------------------------------------
__device__ __forceinline__ void bf16_split2(float e, float o, unsigned& hi, unsigned& lo) {
    __nv_bfloat162 h2 = __floats2bfloat162_rn(e, o);
    hi = *(unsigned*)&h2;
    float re = e - __bfloat162float(h2.x);
    float ro = o - __bfloat162float(h2.y);
    __nv_bfloat162 l2 = __floats2bfloat162_rn(re, ro);
    lo = *(unsigned*)&l2;
}
__device__ __forceinline__ unsigned h2pack(float e, float o) {
    __half2 h = __floats2half2_rn(e, o);
    return *(unsigned*)&h;
}
__device__ __forceinline__ void mma16(float* c, const unsigned* a, const unsigned* b) {
    asm volatile("mma.sync.aligned.m16n8k16.row.col.f32.bf16.bf16.f32 "
                 "{%0,%1,%2,%3}, {%4,%5,%6,%7}, {%8,%9}, {%0,%1,%2,%3};"
                 : "+f"(c[0]), "+f"(c[1]), "+f"(c[2]), "+f"(c[3])
                 : "r"(a[0]), "r"(a[1]), "r"(a[2]), "r"(a[3]),
                   "r"(b[0]), "r"(b[1]));
}
__device__ __forceinline__ void mma16h(float* c, const unsigned* a, const unsigned* b) {
    asm volatile("mma.sync.aligned.m16n8k16.row.col.f32.f16.f16.f32 "
                 "{%0,%1,%2,%3}, {%4,%5,%6,%7}, {%8,%9}, {%0,%1,%2,%3};"
                 : "+f"(c[0]), "+f"(c[1]), "+f"(c[2]), "+f"(c[3])
                 : "r"(a[0]), "r"(a[1]), "r"(a[2]), "r"(a[3]),
                   "r"(b[0]), "r"(b[1]));
}
__device__ __forceinline__ void ldsm4(unsigned& r0, unsigned& r1, unsigned& r2,
                                      unsigned& r3, const void* p) {
    unsigned a = (unsigned)__cvta_generic_to_shared(p);
    asm volatile("ldmatrix.sync.aligned.m8n8.x4.shared.b16 {%0,%1,%2,%3}, [%4];"
                 : "=r"(r0), "=r"(r1), "=r"(r2), "=r"(r3) : "r"(a));
}
__device__ __forceinline__ void ldsm4t(unsigned& r0, unsigned& r1, unsigned& r2,
                                       unsigned& r3, const void* p) {
    unsigned a = (unsigned)__cvta_generic_to_shared(p);
    asm volatile("ldmatrix.sync.aligned.m8n8.x4.trans.shared.b16 {%0,%1,%2,%3}, [%4];"
                 : "=r"(r0), "=r"(r1), "=r"(r2), "=r"(r3) : "r"(a));
}
__device__ __forceinline__ void cp16(void* sdst, const void* gsrc) {
    unsigned u = (unsigned)__cvta_generic_to_shared(sdst);
    asm volatile("cp.async.ca.shared.global [%0], [%1], 16;" :: "r"(u), "l"(gsrc));
}
#define CP_COMMIT() asm volatile("cp.async.commit_group;")
#define CP_WAIT(n)  asm volatile("cp.async.wait_group %0;" :: "n"(n))

// ---------------- fused split: weights + x (bf16 hi/lo pairs) ------------------
#define NW2 (4 * DIMC * DIMC / 2)
#define NX2 (BATCH * NTOK * DIMC / 2)
__global__ void split_kernel(const float* __restrict__ qkvw,
                             const float* __restrict__ projw,
                             const float* __restrict__ x) {
    int i = blockIdx.x * 256 + threadIdx.x;
    unsigned h, l;
    if (i < NW2) {
        int nq2 = 3 * DIMC * DIMC / 2;
        float2 v = (i < nq2) ? ((const float2*)qkvw)[i] : ((const float2*)projw)[i - nq2];
        bf16_split2(v.x, v.y, h, l);
        g_wh[i] = h; g_wl[i] = l;
    } else {
        int j = i - NW2;
        float2 v = ((const float2*)x)[j];
        bf16_split2(v.x, v.y, h, l);
        g_xh[j] = h; g_xl[j] = l;
    }
}

// ---------------- CPB MLP t[r][h] ---------------------------------------------
__global__ void cpb_kernel(const float* __restrict__ table,
                           const float* __restrict__ fc1w,
                           const float* __restrict__ fc1b,
                           const float* __restrict__ fc2w,
                           const float* __restrict__ fc2b) {
    __shared__ float hid[512];
    int r = blockIdx.x;
    int j = threadIdx.x;
    float c0 = table[r * 2 + 0];
    float c1 = table[r * 2 + 1];
    float hv = c0 * fc1w[j * 2 + 0] + c1 * fc1w[j * 2 + 1] + fc1b[j];
    hid[j] = fmaxf(hv, 0.0f);
    __syncthreads();
    int w = j >> 5;
    int lane = j & 31;
    float acc = 0.0f;
#pragma unroll
    for (int kk = lane; kk < 512; kk += 32) acc += hid[kk] * fc2w[w * 512 + kk];
#pragma unroll
    for (int off = 16; off >= 1; off >>= 1) acc += __shfl_xor_sync(0xffffffffu, acc, off);
    if (lane == 0) g_t[r * NH + w] = acc + fc2b[w];
}

// ---------------- bias gather  biash[h][n][m] = half(t[rpi[n][m]][h]) ---------
__global__ void bias_kernel(const int* __restrict__ rpi) {
    int n = blockIdx.x;
    for (int m = threadIdx.x; m < NTOK; m += blockDim.x) {
        int idx = rpi[n * NTOK + m];
        const float4* tp = (const float4*)(g_t + idx * NH);
        float4 t0 = tp[0], t1 = tp[1], t2 = tp[2], t3 = tp[3];
        float v[16] = {t0.x, t0.y, t0.z, t0.w, t1.x, t1.y, t1.z, t1.w,
                       t2.x, t2.y, t2.z, t2.w, t3.x, t3.y, t3.z, t3.w};
#pragma unroll
        for (int h = 0; h < NH; h++)
            g_biash[((size_t)h * NTOK + n) * NTOK + m] = __float2half(v[h]);
    }
}

// ================ shared GEMM mainloop (macro) =================================
#define GEMM_SMEM (4 * 2 * 128 * 20 * 4)
#define GEMM_MAIN(Ah, Al, Wh, Wl, K)                                              \
    extern __shared__ unsigned smg[];                                             \
    unsigned* Ahs = smg;                                                          \
    unsigned* Als = smg + 2 * 2560;                                               \
    unsigned* Whs = smg + 4 * 2560;                                               \
    unsigned* Wls = smg + 6 * 2560;                                               \
    int tid = threadIdx.x;                                                        \
    int wid = tid >> 5, lane = tid & 31;                                          \
    int g = lane >> 2, tg = lane & 3;                                             \
    int wm = wid & 3, wn = wid >> 2;                                              \
    int m0 = blockIdx.y * 128, n0 = blockIdx.x * 128;                             \
    int KU = (K) >> 1;                                                            \
    int lrow = tid >> 2, lch = (tid & 3) * 4;                                     \
    int a_r = (lane & 15), a_c = (lane >> 4) * 4;                                 \
    int b_r = (lane >> 4) * 8 + (lane & 7), b_c = ((lane >> 3) & 1) * 4;          \
    float acc[2][8][4];                                                           \
    _Pragma("unroll") for (int mi = 0; mi < 2; mi++)                              \
        _Pragma("unroll") for (int j = 0; j < 8; j++)                             \
            _Pragma("unroll") for (int c = 0; c < 4; c++) acc[mi][j][c] = 0.0f;   \
    int nk = (K) >> 5;                                                            \
    G_LOAD(Ah, Al, Wh, Wl, 0, 0);                                                 \
    for (int i = 0; i < nk; i++) {                                                \
        if (i + 1 < nk) { G_LOAD(Ah, Al, Wh, Wl, (i + 1) & 1, (i + 1) << 4); CP_WAIT(1); } \
        else { CP_WAIT(0); }                                                      \
        __syncthreads();                                                          \
        int s = i & 1;                                                            \
        const unsigned* Ahb = Ahs + s * 2560;                                     \
        const unsigned* Alb = Als + s * 2560;                                     \
        const unsigned* Whb = Whs + s * 2560;                                     \
        const unsigned* Wlb = Wls + s * 2560;                                     \
        _Pragma("unroll") for (int kt = 0; kt < 2; kt++) {                        \
            unsigned ah[2][4], al[2][4];                                          \
            _Pragma("unroll") for (int mi = 0; mi < 2; mi++) {                    \
                int row = wm * 32 + mi * 16 + a_r;                                \
                int col = kt * 8 + a_c;                                           \
                ldsm4(ah[mi][0], ah[mi][1], ah[mi][2], ah[mi][3], &Ahb[row * 20 + col]); \
                ldsm4(al[mi][0], al[mi][1], al[mi][2], al[mi][3], &Alb[row * 20 + col]); \
            }                                                                     \
            unsigned bh[2][4], bl[2][4];                                          \
            {                                                                     \
                int row = wn * 64 + b_r;                                          \
                int col = kt * 8 + b_c;                                           \
                ldsm4(bh[0][0], bh[0][1], bh[0][2], bh[0][3], &Whb[row * 20 + col]); \
                ldsm4(bl[0][0], bl[0][1], bl[0][2], bl[0][3], &Wlb[row * 20 + col]); \
            }                                                                     \
            _Pragma("unroll") for (int jp = 0; jp < 4; jp++) {                    \
                int cur = jp & 1;                                                 \
                if (jp < 3) {                                                     \
                    int row = wn * 64 + (jp + 1) * 16 + b_r;                      \
                    int col = kt * 8 + b_c;                                       \
                    ldsm4(bh[cur ^ 1][0], bh[cur ^ 1][1], bh[cur ^ 1][2], bh[cur ^ 1][3], \
                          &Whb[row * 20 + col]);                                  \
                    ldsm4(bl[cur ^ 1][0], bl[cur ^ 1][1], bl[cur ^ 1][2], bl[cur ^ 1][3], \
                          &Wlb[row * 20 + col]);                                  \
                }                                                                 \
                _Pragma("unroll") for (int mi = 0; mi < 2; mi++) {                \
                    mma16(acc[mi][jp * 2], ah[mi], bh[cur]);                      \
                    mma16(acc[mi][jp * 2], ah[mi], bl[cur]);                      \
                    mma16(acc[mi][jp * 2], al[mi], bh[cur]);                      \
                    mma16(acc[mi][jp * 2 + 1], ah[mi], bh[cur] + 2);              \
                    mma16(acc[mi][jp * 2 + 1], ah[mi], bl[cur] + 2);              \
                    mma16(acc[mi][jp * 2 + 1], al[mi], bh[cur] + 2);              \
                }                                                                 \
            }                                                                     \
        }                                                                         \
        __syncthreads();                                                          \
    }

#define G_LOAD(Ah, Al, Wh, Wl, stage, ku0)                                        \
    do {                                                                          \
        cp16(&Ahs[(stage) * 2560 + lrow * 20 + lch], Ah + (size_t)(m0 + lrow) * KU + (ku0) + lch);          \
        cp16(&Ahs[(stage) * 2560 + (lrow + 64) * 20 + lch], Ah + (size_t)(m0 + lrow + 64) * KU + (ku0) + lch); \
        cp16(&Als[(stage) * 2560 + lrow * 20 + lch], Al + (size_t)(m0 + lrow) * KU + (ku0) + lch);          \
        cp16(&Als[(stage) * 2560 + (lrow + 64) * 20 + lch], Al + (size_t)(m0 + lrow + 64) * KU + (ku0) + lch); \
        cp16(&Whs[(stage) * 2560 + lrow * 20 + lch], Wh + (size_t)(n0 + lrow) * KU + (ku0) + lch);          \
        cp16(&Whs[(stage) * 2560 + (lrow + 64) * 20 + lch], Wh + (size_t)(n0 + lrow + 64) * KU + (ku0) + lch); \
        cp16(&Wls[(stage) * 2560 + lrow * 20 + lch], Wl + (size_t)(n0 + lrow) * KU + (ku0) + lch);          \
        cp16(&Wls[(stage) * 2560 + (lrow + 64) * 20 + lch], Wl + (size_t)(n0 + lrow + 64) * KU + (ku0) + lch); \
        CP_COMMIT();                                                              \
    } while (0)

// ---------------- generic GEMM (proj): fp32 + bias epilogue --------------------
__global__ __launch_bounds__(256, 2) void gemm3b(const unsigned* __restrict__ Ah,
                                                 const unsigned* __restrict__ Al,
                                                 const unsigned* __restrict__ Wh,
                                                 const unsigned* __restrict__ Wl,
                                                 const float* __restrict__ bias,
                                                 float* __restrict__ C,
                                                 int M, int Nn, int K) {
    GEMM_MAIN(Ah, Al, Wh, Wl, K)
#pragma unroll
    for (int j = 0; j < 8; j++) {
        int col = n0 + wn * 64 + j * 8 + tg * 2;
        float2 bv = *(const float2*)(bias + col);
#pragma unroll
        for (int mi = 0; mi < 2; mi++) {
            int row = m0 + wm * 32 + mi * 16 + g;
            float2 o0 = make_float2(acc[mi][j][0] + bv.x, acc[mi][j][1] + bv.y);
            float2 o1 = make_float2(acc[mi][j][2] + bv.x, acc[mi][j][3] + bv.y);
            *(float2*)(C + (size_t)row * Nn + col) = o0;
            *(float2*)(C + (size_t)(row + 8) * Nn + col) = o1;
        }
    }
}

// ---------------- qkv GEMM with fused reorg epilogue ---------------------------
// grid (12, 64). bx 0-3: q cols, 4-7: k, 8-11: v. Normalizes q/k per head
// (quad reduction), applies qe+softplus scale to q, packs bf16 hi/lo (q,k)
// or fp16 (v), stores directly in attention layout [b,h,n,16 pairs].
__global__ __launch_bounds__(256, 2) void gemm_qkv(const unsigned* __restrict__ Ah,
                                                   const unsigned* __restrict__ Al,
                                                   const unsigned* __restrict__ Wh,
                                                   const unsigned* __restrict__ Wl,
                                                   const float* __restrict__ bias,
                                                   const float* __restrict__ qe,
                                                   const float* __restrict__ temp,
                                                   int K) {
    GEMM_MAIN(Ah, Al, Wh, Wl, K)
    int bx = blockIdx.x;
    int type = bx >> 2;                      // 0=q, 1=k, 2=v
    int h0 = (bx & 3) * 4 + wn * 2;          // head for j<4; j>=4 -> h0+1
    // bias add
#pragma unroll
    for (int j = 0; j < 8; j++) {
        int col = n0 + wn * 64 + j * 8 + tg * 2;
        float2 bv = *(const float2*)(bias + col);
#pragma unroll
        for (int mi = 0; mi < 2; mi++) {
            acc[mi][j][0] += bv.x; acc[mi][j][1] += bv.y;
            acc[mi][j][2] += bv.x; acc[mi][j][3] += bv.y;
        }
    }
    if (type < 2) {
        // per-head L2 normalize (quad reduction over 32 dims)
#pragma unroll
        for (int mi = 0; mi < 2; mi++) {
#pragma unroll
            for (int half = 0; half < 2; half++) {
                float s0 = 0.0f, s1 = 0.0f;
#pragma unroll
                for (int jj = 0; jj < 4; jj++) {
                    int j = half * 4 + jj;
                    s0 += acc[mi][j][0] * acc[mi][j][0] + acc[mi][j][1] * acc[mi][j][1];
                    s1 += acc[mi][j][2] * acc[mi][j][2] + acc[mi][j][3] * acc[mi][j][3];
                }
                s0 += __shfl_xor_sync(0xffffffffu, s0, 1);
                s0 += __shfl_xor_sync(0xffffffffu, s0, 2);
                s1 += __shfl_xor_sync(0xffffffffu, s1, 1);
                s1 += __shfl_xor_sync(0xffffffffu, s1, 2);
                float inv0 = 1.0f / fmaxf(sqrtf(s0), 1e-12f);
                float inv1 = 1.0f / fmaxf(sqrtf(s1), 1e-12f);
#pragma unroll
                for (int jj = 0; jj < 4; jj++) {
                    int j = half * 4 + jj;
                    acc[mi][j][0] *= inv0; acc[mi][j][1] *= inv0;
                    acc[mi][j][2] *= inv1; acc[mi][j][3] *= inv1;
                }
            }
        }
        if (type == 0) {
            float t0 = temp[h0], t1 = temp[h0 + 1];
            float sc0 = ((t0 > 20.0f) ? t0 : log1pf(expf(t0))) * SEQ_SCALE;
            float sc1 = ((t1 > 20.0f) ? t1 : log1pf(expf(t1))) * SEQ_SCALE;
#pragma unroll
            for (int j = 0; j < 8; j++) {
                int h = h0 + (j >> 2);
                float sc = (j >> 2) ? sc1 : sc0;
                int d = (j & 3) * 8 + tg * 2;
                float2 q2 = *(const float2*)(qe + h * HD + d);
#pragma unroll
                for (int mi = 0; mi < 2; mi++) {
                    acc[mi][j][0] = (acc[mi][j][0] + q2.x) * sc;
                    acc[mi][j][1] = (acc[mi][j][1] + q2.y) * sc;
                    acc[mi][j][2] = (acc[mi][j][2] + q2.x) * sc;
                    acc[mi][j][3] = (acc[mi][j][3] + q2.y) * sc;
                }
            }
        }
        unsigned* Dh = (type == 0) ? g_qh : g_kh;
        unsigned* Dl = (type == 0) ? g_ql : g_kl;
#pragma unroll
        for (int j = 0; j < 8; j++) {
            int h = h0 + (j >> 2);
            int pc = (j & 3) * 4 + tg;
#pragma unroll
            for (int mi = 0; mi < 2; mi++) {
                int row = m0 + wm * 32 + mi * 16 + g;
                int bb = row >> 10, nn = row & 1023;
                size_t base = ((size_t)(bb * NH + h) * NTOK + nn) * 16 + pc;
                unsigned hw, lw;
                bf16_split2(acc[mi][j][0], acc[mi][j][1], hw, lw);
                Dh[base] = hw; Dl[base] = lw;
                int row2 = row + 8;
                int bb2 = row2 >> 10, nn2 = row2 & 1023;
                size_t base2 = ((size_t)(bb2 * NH + h) * NTOK + nn2) * 16 + pc;
                bf16_split2(acc[mi][j][2], acc[mi][j][3], hw, lw);
                Dh[base2] = hw; Dl[base2] = lw;
            }
        }
    } else {
        // v: pack fp16 pairs
#pragma unroll
        for (int j = 0; j < 8; j++) {
            int h = h0 + (j >> 2);
            int pc = (j & 3) * 4 + tg;
#pragma unroll
            for (int mi = 0; mi < 2; mi++) {
                int row = m0 + wm * 32 + mi * 16 + g;
                int bb = row >> 10, nn = row & 1023;
                g_vh[((size_t)(bb * NH + h) * NTOK + nn) * 16 + pc] =
                    h2pack(acc[mi][j][0], acc[mi][j][1]);
                int row2 = row + 8;
                int bb2 = row2 >> 10, nn2 = row2 & 1023;
                g_vh[((size_t)(bb2 * NH + h) * NTOK + nn2) * 16 + pc] =
                    h2pack(acc[mi][j][2], acc[mi][j][3]);
            }
        }
    }
}

// ---------------- attention v13: online softmax + register-P fp16 PV -----------
#define ATTN_SMEM ((3 * 2560 + 9216) * 4)
__global__ __launch_bounds__(256, 2) void attn13_kernel() {
    extern __shared__ unsigned smu[];
    unsigned* Khs = smu;                     // [2][1280]
    unsigned* Kls = smu + 2560;
    unsigned* Vhs = smu + 5120;              // [2][1280]
    __half*  BBh = (__half*)(smu + 7680);    // [2][128*72]

    int b = blockIdx.x, qt = blockIdx.y, h = blockIdx.z;
    int tid = threadIdx.x;
    int w = tid >> 5, lane = tid & 31;
    int g = lane >> 2, tg = lane & 3;

    size_t bh16 = (size_t)(b * NH + h) * NTOK * (HD / 2);
    const unsigned* qhb = g_qh + bh16 + (size_t)qt * 128 * (HD / 2);
    const unsigned* qlb = g_ql + bh16 + (size_t)qt * 128 * (HD / 2);
    const unsigned* khb = g_kh + bh16;
    const unsigned* klb = g_kl + bh16;
    const unsigned* vhb = g_vh + bh16;
    const __half* bbh = g_biash + ((size_t)h * NTOK + qt * 128) * NTOK;

    int krow = tid >> 2, kch = (tid & 3) * 4;
    int brow = tid >> 3, bch = (tid & 7) * 8;
    int b_r = (lane >> 4) * 8 + (lane & 7), b_c = ((lane >> 3) & 1) * 4;
    int v_r = ((lane >> 3) & 1) * 8 + (lane & 7), v_c = (lane >> 4) * 4;
#define KVB_LOAD(stage, mt_)                                                      \
    do {                                                                          \
        cp16(&Khs[(stage) * 1280 + krow * 20 + kch], khb + (size_t)((mt_) * 64 + krow) * 16 + kch); \
        cp16(&Kls[(stage) * 1280 + krow * 20 + kch], klb + (size_t)((mt_) * 64 + krow) * 16 + kch); \
        cp16(&Vhs[(stage) * 1280 + krow * 20 + kch], vhb + (size_t)((mt_) * 64 + krow) * 16 + kch); \
        _Pragma("unroll")                                                         \
        for (int p = 0; p < 4; p++) {                                             \
            int row = brow + p * 32;                                              \
            cp16(&BBh[(stage) * 9216 + row * 72 + bch],                           \
                 bbh + (size_t)row * NTOK + (mt_) * 64 + bch);                    \
        }                                                                         \
        CP_COMMIT();                                                              \
    } while (0)

    KVB_LOAD(0, 0);

    unsigned Qh[2][4], Ql[2][4];
    int r = w * 16 + g;
#pragma unroll
    for (int kt = 0; kt < 2; kt++) {
        int c = kt * 8 + tg;
        Qh[kt][0] = qhb[r * 16 + c];           Ql[kt][0] = qlb[r * 16 + c];
        Qh[kt][1] = qhb[(r + 8) * 16 + c];     Ql[kt][1] = qlb[(r + 8) * 16 + c];
        Qh[kt][2] = qhb[r * 16 + c + 4];       Ql[kt][2] = qlb[r * 16 + c + 4];
        Qh[kt][3] = qhb[(r + 8) * 16 + c + 4]; Ql[kt][3] = qlb[(r + 8) * 16 + c + 4];
    }

    float m0 = -INFINITY, m1 = -INFINITY, l0 = 0.0f, l1 = 0.0f;
    float O[4][4];
#pragma unroll
    for (int j = 0; j < 4; j++)
#pragma unroll
        for (int c = 0; c < 4; c++) O[j][c] = 0.0f;

    for (int mt = 0; mt < 16; mt++) {
        int s = mt & 1;
        CP_WAIT(0);
        __syncthreads();   // tile mt visible; all warps done reading stage s^1
        if (mt + 1 < 16) KVB_LOAD(s ^ 1, mt + 1);

        float S[8][4];
#pragma unroll
        for (int j = 0; j < 8; j++)
#pragma unroll
            for (int c = 0; c < 4; c++) S[j][c] = 0.0f;
        const unsigned* Khb = Khs + s * 1280;
        const unsigned* Klb = Kls + s * 1280;
        unsigned bh2[2][4], bl2[2][4];
        {
            ldsm4(bh2[0][0], bh2[0][1], bh2[0][2], bh2[0][3], &Khb[b_r * 20 + b_c]);
            ldsm4(bl2[0][0], bl2[0][1], bl2[0][2], bl2[0][3], &Klb[b_r * 20 + b_c]);
        }
#pragma unroll
        for (int u = 0; u < 8; u++) {
            int kt = u >> 2, jp = u & 3;
            int cur = u & 1;
            if (u < 7) {
                int nkt = (u + 1) >> 2, njp = (u + 1) & 3;
                int row = njp * 16 + b_r;
                int col = nkt * 8 + b_c;
                ldsm4(bh2[cur ^ 1][0], bh2[cur ^ 1][1], bh2[cur ^ 1][2], bh2[cur ^ 1][3],
                      &Khb[row * 20 + col]);
                ldsm4(bl2[cur ^ 1][0], bl2[cur ^ 1][1], bl2[cur ^ 1][2], bl2[cur ^ 1][3],
                      &Klb[row * 20 + col]);
            }
            mma16(S[jp * 2], Qh[kt], bh2[cur]);
            mma16(S[jp * 2], Qh[kt], bl2[cur]);
            mma16(S[jp * 2], Ql[kt], bh2[cur]);
            mma16(S[jp * 2 + 1], Qh[kt], bh2[cur] + 2);
            mma16(S[jp * 2 + 1], Qh[kt], bl2[cur] + 2);
            mma16(S[jp * 2 + 1], Ql[kt], bh2[cur] + 2);
        }
        const __half* Bb = BBh + s * 9216;
#pragma unroll
        for (int j = 0; j < 8; j++) {
            float2 b0 = __half22float2(*(const __half2*)(Bb + r * 72 + j * 8 + tg * 2));
            float2 b1 = __half22float2(*(const __half2*)(Bb + (r + 8) * 72 + j * 8 + tg * 2));
            S[j][0] += b0.x; S[j][1] += b0.y;
            S[j][2] += b1.x; S[j][3] += b1.y;
        }
        float mx0 = -INFINITY, mx1 = -INFINITY;
#pragma unroll
        for (int j = 0; j < 8; j++) {
            mx0 = fmaxf(mx0, fmaxf(S[j][0], S[j][1]));
            mx1 = fmaxf(mx1, fmaxf(S[j][2], S[j][3]));
        }
        mx0 = fmaxf(mx0, __shfl_xor_sync(0xffffffffu, mx0, 1));
        mx0 = fmaxf(mx0, __shfl_xor_sync(0xffffffffu, mx0, 2));
        mx1 = fmaxf(mx1, __shfl_xor_sync(0xffffffffu, mx1, 1));
        mx1 = fmaxf(mx1, __shfl_xor_sync(0xffffffffu, mx1, 2));
        float mn0 = fmaxf(m0, mx0), mn1 = fmaxf(m1, mx1);
        float alpha0 = __expf(m0 - mn0), alpha1 = __expf(m1 - mn1);
        m0 = mn0; m1 = mn1;
        float rs0 = 0.0f, rs1 = 0.0f;
#pragma unroll
        for (int j = 0; j < 8; j++) {
            S[j][0] = __expf(S[j][0] - mn0);
            S[j][1] = __expf(S[j][1] - mn0);
            S[j][2] = __expf(S[j][2] - mn1);
            S[j][3] = __expf(S[j][3] - mn1);
            rs0 += S[j][0] + S[j][1];
            rs1 += S[j][2] + S[j][3];
        }
        rs0 += __shfl_xor_sync(0xffffffffu, rs0, 1);
        rs0 += __shfl_xor_sync(0xffffffffu, rs0, 2);
        rs1 += __shfl_xor_sync(0xffffffffu, rs1, 1);
        rs1 += __shfl_xor_sync(0xffffffffu, rs1, 2);
        l0 = l0 * alpha0 + rs0;
        l1 = l1 * alpha1 + rs1;
#pragma unroll
        for (int j = 0; j < 4; j++) {
            O[j][0] *= alpha0; O[j][1] *= alpha0;
            O[j][2] *= alpha1; O[j][3] *= alpha1;
        }
        unsigned Pa[4][4];
#pragma unroll
        for (int kt = 0; kt < 4; kt++) {
            Pa[kt][0] = h2pack(S[2 * kt][0], S[2 * kt][1]);
            Pa[kt][1] = h2pack(S[2 * kt][2], S[2 * kt][3]);
            Pa[kt][2] = h2pack(S[2 * kt + 1][0], S[2 * kt + 1][1]);
            Pa[kt][3] = h2pack(S[2 * kt + 1][2], S[2 * kt + 1][3]);
        }
        const unsigned* Vb = Vhs + s * 1280;
#pragma unroll
        for (int kt = 0; kt < 4; kt++) {
            int row = kt * 16 + v_r;
            unsigned bv[8];
            ldsm4t(bv[0], bv[1], bv[2], bv[3], &Vb[row * 20 + v_c]);
            ldsm4t(bv[4], bv[5], bv[6], bv[7], &Vb[row * 20 + 8 + v_c]);
            mma16h(O[0], Pa[kt], bv + 0);
            mma16h(O[1], Pa[kt], bv + 2);
            mma16h(O[2], Pa[kt], bv + 4);
            mma16h(O[3], Pa[kt], bv + 6);
        }
    }
    float inv0 = 1.0f / l0, inv1 = 1.0f / l1;
    int q0r = qt * 128 + w * 16 + g;
    size_t row0 = (size_t)b * NTOK + q0r;
    int colbase = h * 16;
#pragma unroll
    for (int j = 0; j < 4; j++) {
        unsigned hw, lw;
        bf16_split2(O[j][0] * inv0, O[j][1] * inv0, hw, lw);
        g_oh[row0 * 256 + colbase + j * 4 + tg] = hw;
        g_ol[row0 * 256 + colbase + j * 4 + tg] = lw;
        bf16_split2(O[j][2] * inv1, O[j][3] * inv1, hw, lw);
        g_oh[(row0 + 8) * 256 + colbase + j * 4 + tg] = hw;
        g_ol[(row0 + 8) * 256 + colbase + j * 4 + tg] = lw;
    }
}

// ---------------- launcher: fork-join streams under graph capture --------------
extern "C" void kernel_launch(void* const* d_in, const int* in_sizes, int n_in,
                              void* d_out, int out_size) {
    const float* x      = (const float*)d_in[0];
    const int*   rpi    = (const int*)d_in[3];
    const float* table  = (const float*)d_in[4];
    const float* qkv_w  = (const float*)d_in[5];
    const float* qkv_b  = (const float*)d_in[6];
    const float* proj_w = (const float*)d_in[7];
    const float* proj_b = (const float*)d_in[8];
    const float* temp   = (const float*)d_in[9];
    const float* qe     = (const float*)d_in[10];
    const float* fc1w   = (const float*)d_in[11];
    const float* fc1b   = (const float*)d_in[12];
    const float* fc2w   = (const float*)d_in[13];
    const float* fc2b   = (const float*)d_in[14];
    float* out = (float*)d_out;

    unsigned* p_wh; cudaGetSymbolAddress((void**)&p_wh, g_wh);
    unsigned* p_wl; cudaGetSymbolAddress((void**)&p_wl, g_wl);
    unsigned* p_xh; cudaGetSymbolAddress((void**)&p_xh, g_xh);
    unsigned* p_xl; cudaGetSymbolAddress((void**)&p_xl, g_xl);
    unsigned* p_oh; cudaGetSymbolAddress((void**)&p_oh, g_oh);
    unsigned* p_ol; cudaGetSymbolAddress((void**)&p_ol, g_ol);

    static int attr_set = 0;
    static cudaStream_t s2;
    static cudaEvent_t e_fork, e_join;
    if (!attr_set) {
        cudaFuncSetAttribute(attn13_kernel, cudaFuncAttributeMaxDynamicSharedMemorySize,
                             ATTN_SMEM);
        cudaFuncSetAttribute(gemm3b, cudaFuncAttributeMaxDynamicSharedMemorySize,
                             GEMM_SMEM);
        cudaFuncSetAttribute(gemm_qkv, cudaFuncAttributeMaxDynamicSharedMemorySize,
                             GEMM_SMEM);
        cudaStreamCreateWithFlags(&s2, cudaStreamNonBlocking);
        cudaEventCreateWithFlags(&e_fork, cudaEventDisableTiming);
        cudaEventCreateWithFlags(&e_join, cudaEventDisableTiming);
        attr_set = 1;
    }

    // fork: cpb -> bias on side stream (independent of main chain)
    cudaEventRecord(e_fork, 0);
    cudaStreamWaitEvent(s2, e_fork, 0);
    cpb_kernel<<<TABLE_SZ, 512, 0, s2>>>(table, fc1w, fc1b, fc2w, fc2b);
    bias_kernel<<<NTOK, 256, 0, s2>>>(rpi);
    cudaEventRecord(e_join, s2);

    // main chain: split -> fused qkv gemm (writes q/k/v attention-layout directly)
    split_kernel<<<(NW2 + NX2) / 256, 256>>>(qkv_w, proj_w, x);
    {
        dim3 grid(3 * DIMC / 128, BATCH * NTOK / 128);
        gemm_qkv<<<grid, 256, GEMM_SMEM>>>(p_xh, p_xl, p_wh, p_wl, qkv_b,
                                           qe, temp, DIMC);
    }

    // join: attention needs bias
    cudaStreamWaitEvent(0, e_join, 0);
    {
        dim3 grid(BATCH, NTOK / 128, NH);
        attn13_kernel<<<grid, 256, ATTN_SMEM>>>();
    }
    {
        dim3 grid(DIMC / 128, BATCH * NTOK / 128);
        gemm3b<<<grid, 256, GEMM_SMEM>>>(p_oh, p_ol, p_wh + 3 * DIMC * DIMC / 2,
                                         p_wl + 3 * DIMC * DIMC / 2, proj_b, out,
                                         BATCH * NTOK, DIMC, DIMC);
    }
}

// round 16
// speedup vs baseline: 1.3422x; 1.0181x over previous
#include <cuda_runtime.h>
#include <cuda_bf16.h>
#include <cuda_fp16.h>
#include <math.h>

// Problem constants
#define BATCH 8
#define NTOK 1024
#define DIMC 512
#define NH 16
#define HD 32
#define TABLE_SZ 3969
#define SEQ_SCALE 6.93147180559945309f  // ln(1024)

// ---------------- scratch (device globals; no allocation allowed) -------------
__device__ float g_t[TABLE_SZ * NH];
__device__ __half g_biash[NH * NTOK * NTOK];            // [h][n][m] 32MB fp16
__device__ unsigned g_qh[BATCH * NH * NTOK * HD / 2];   // q hi, packed bf16 pairs
__device__ unsigned g_ql[BATCH * NH * NTOK * HD / 2];   // q lo
__device__ unsigned g_kh[BATCH * NH * NTOK * HD / 2];   // k hi
__device__ unsigned g_kl[BATCH * NH * NTOK * HD / 2];   // k lo
__device__ unsigned g_vh[BATCH * NH * NTOK * HD / 2];   // v fp16 pairs [key][d]
__device__ unsigned g_oh[BATCH * NTOK * DIMC / 2];      // attn out hi (bf16 pairs)
__device__ unsigned g_ol[BATCH * NTOK * DIMC / 2];      // attn out lo
__device__ unsigned g_xh[BATCH * NTOK * DIMC / 2];      // x hi
__device__ unsigned g_xl[BATCH * NTOK * DIMC / 2];      // x lo
__device__ unsigned g_wh[(3 * DIMC + DIMC) * DIMC / 2]; // W hi (qkv then proj)
__device__ unsigned g_wl[(3 * DIMC + DIMC) * DIMC / 2]; // W lo

// ---------------- helpers -----------------------------------------------------
__device__ __forceinline__ void bf16_split2(float e, float o, unsigned& hi, unsigned& lo) {
    __nv_bfloat162 h2 = __floats2bfloat162_rn(e, o);
    hi = *(unsigned*)&h2;
    float re = e - __bfloat162float(h2.x);
    float ro = o - __bfloat162float(h2.y);
    __nv_bfloat162 l2 = __floats2bfloat162_rn(re, ro);
    lo = *(unsigned*)&l2;
}
__device__ __forceinline__ unsigned h2pack(float e, float o) {
    __half2 h = __floats2half2_rn(e, o);
    return *(unsigned*)&h;
}
__device__ __forceinline__ void mma16(float* c, const unsigned* a, const unsigned* b) {
    asm volatile("mma.sync.aligned.m16n8k16.row.col.f32.bf16.bf16.f32 "
                 "{%0,%1,%2,%3}, {%4,%5,%6,%7}, {%8,%9}, {%0,%1,%2,%3};"
                 : "+f"(c[0]), "+f"(c[1]), "+f"(c[2]), "+f"(c[3])
                 : "r"(a[0]), "r"(a[1]), "r"(a[2]), "r"(a[3]),
                   "r"(b[0]), "r"(b[1]));
}
__device__ __forceinline__ void mma16h(float* c, const unsigned* a, const unsigned* b) {
    asm volatile("mma.sync.aligned.m16n8k16.row.col.f32.f16.f16.f32 "
                 "{%0,%1,%2,%3}, {%4,%5,%6,%7}, {%8,%9}, {%0,%1,%2,%3};"
                 : "+f"(c[0]), "+f"(c[1]), "+f"(c[2]), "+f"(c[3])
                 : "r"(a[0]), "r"(a[1]), "r"(a[2]), "r"(a[3]),
                   "r"(b[0]), "r"(b[1]));
}
__device__ __forceinline__ void ldsm4(unsigned& r0, unsigned& r1, unsigned& r2,
                                      unsigned& r3, const void* p) {
    unsigned a = (unsigned)__cvta_generic_to_shared(p);
    asm volatile("ldmatrix.sync.aligned.m8n8.x4.shared.b16 {%0,%1,%2,%3}, [%4];"
                 : "=r"(r0), "=r"(r1), "=r"(r2), "=r"(r3) : "r"(a));
}
__device__ __forceinline__ void ldsm4t(unsigned& r0, unsigned& r1, unsigned& r2,
                                       unsigned& r3, const void* p) {
    unsigned a = (unsigned)__cvta_generic_to_shared(p);
    asm volatile("ldmatrix.sync.aligned.m8n8.x4.trans.shared.b16 {%0,%1,%2,%3}, [%4];"
                 : "=r"(r0), "=r"(r1), "=r"(r2), "=r"(r3) : "r"(a));
}
__device__ __forceinline__ void cp16(void* sdst, const void* gsrc) {
    unsigned u = (unsigned)__cvta_generic_to_shared(sdst);
    asm volatile("cp.async.ca.shared.global [%0], [%1], 16;" :: "r"(u), "l"(gsrc));
}
#define CP_COMMIT() asm volatile("cp.async.commit_group;")
#define CP_WAIT(n)  asm volatile("cp.async.wait_group %0;" :: "n"(n))

// ---------------- fused split: weights + x (bf16 hi/lo pairs) ------------------
#define NW2 (4 * DIMC * DIMC / 2)
#define NX2 (BATCH * NTOK * DIMC / 2)
__global__ void split_kernel(const float* __restrict__ qkvw,
                             const float* __restrict__ projw,
                             const float* __restrict__ x) {
    int i = blockIdx.x * 256 + threadIdx.x;
    unsigned h, l;
    if (i < NW2) {
        int nq2 = 3 * DIMC * DIMC / 2;
        float2 v = (i < nq2) ? ((const float2*)qkvw)[i] : ((const float2*)projw)[i - nq2];
        bf16_split2(v.x, v.y, h, l);
        g_wh[i] = h; g_wl[i] = l;
    } else {
        int j = i - NW2;
        float2 v = ((const float2*)x)[j];
        bf16_split2(v.x, v.y, h, l);
        g_xh[j] = h; g_xl[j] = l;
    }
}

// ---------------- CPB MLP t[r][h] ---------------------------------------------
__global__ void cpb_kernel(const float* __restrict__ table,
                           const float* __restrict__ fc1w,
                           const float* __restrict__ fc1b,
                           const float* __restrict__ fc2w,
                           const float* __restrict__ fc2b) {
    __shared__ float hid[512];
    int r = blockIdx.x;
    int j = threadIdx.x;
    float c0 = table[r * 2 + 0];
    float c1 = table[r * 2 + 1];
    float hv = c0 * fc1w[j * 2 + 0] + c1 * fc1w[j * 2 + 1] + fc1b[j];
    hid[j] = fmaxf(hv, 0.0f);
    __syncthreads();
    int w = j >> 5;
    int lane = j & 31;
    float acc = 0.0f;
#pragma unroll
    for (int kk = lane; kk < 512; kk += 32) acc += hid[kk] * fc2w[w * 512 + kk];
#pragma unroll
    for (int off = 16; off >= 1; off >>= 1) acc += __shfl_xor_sync(0xffffffffu, acc, off);
    if (lane == 0) g_t[r * NH + w] = acc + fc2b[w];
}

// ---------------- bias gather  biash[h][n][m] = half(t[rpi[n][m]][h]) ---------
__global__ void bias_kernel(const int* __restrict__ rpi) {
    int n = blockIdx.x;
    for (int m = threadIdx.x; m < NTOK; m += blockDim.x) {
        int idx = rpi[n * NTOK + m];
        const float4* tp = (const float4*)(g_t + idx * NH);
        float4 t0 = tp[0], t1 = tp[1], t2 = tp[2], t3 = tp[3];
        float v[16] = {t0.x, t0.y, t0.z, t0.w, t1.x, t1.y, t1.z, t1.w,
                       t2.x, t2.y, t2.z, t2.w, t3.x, t3.y, t3.z, t3.w};
#pragma unroll
        for (int h = 0; h < NH; h++)
            g_biash[((size_t)h * NTOK + n) * NTOK + m] = __float2half(v[h]);
    }
}

// ================ shared GEMM mainloop (macro), term-major MMA ordering ========
#define GEMM_SMEM (4 * 2 * 128 * 20 * 4)
#define GEMM_MAIN(Ah, Al, Wh, Wl, K)                                              \
    extern __shared__ unsigned smg[];                                             \
    unsigned* Ahs = smg;                                                          \
    unsigned* Als = smg + 2 * 2560;                                               \
    unsigned* Whs = smg + 4 * 2560;                                               \
    unsigned* Wls = smg + 6 * 2560;                                               \
    int tid = threadIdx.x;                                                        \
    int wid = tid >> 5, lane = tid & 31;                                          \
    int g = lane >> 2, tg = lane & 3;                                             \
    int wm = wid & 3, wn = wid >> 2;                                              \
    int m0 = blockIdx.y * 128, n0 = blockIdx.x * 128;                             \
    int KU = (K) >> 1;                                                            \
    int lrow = tid >> 2, lch = (tid & 3) * 4;                                     \
    int a_r = (lane & 15), a_c = (lane >> 4) * 4;                                 \
    int b_r = (lane >> 4) * 8 + (lane & 7), b_c = ((lane >> 3) & 1) * 4;          \
    float acc[2][8][4];                                                           \
    _Pragma("unroll") for (int mi = 0; mi < 2; mi++)                              \
        _Pragma("unroll") for (int j = 0; j < 8; j++)                             \
            _Pragma("unroll") for (int c = 0; c < 4; c++) acc[mi][j][c] = 0.0f;   \
    int nk = (K) >> 5;                                                            \
    G_LOAD(Ah, Al, Wh, Wl, 0, 0);                                                 \
    for (int i = 0; i < nk; i++) {                                                \
        if (i + 1 < nk) { G_LOAD(Ah, Al, Wh, Wl, (i + 1) & 1, (i + 1) << 4); CP_WAIT(1); } \
        else { CP_WAIT(0); }                                                      \
        __syncthreads();                                                          \
        int s = i & 1;                                                            \
        const unsigned* Ahb = Ahs + s * 2560;                                     \
        const unsigned* Alb = Als + s * 2560;                                     \
        const unsigned* Whb = Whs + s * 2560;                                     \
        const unsigned* Wlb = Wls + s * 2560;                                     \
        _Pragma("unroll") for (int kt = 0; kt < 2; kt++) {                        \
            unsigned ah[2][4], al[2][4];                                          \
            _Pragma("unroll") for (int mi = 0; mi < 2; mi++) {                    \
                int row = wm * 32 + mi * 16 + a_r;                                \
                int col = kt * 8 + a_c;                                           \
                ldsm4(ah[mi][0], ah[mi][1], ah[mi][2], ah[mi][3], &Ahb[row * 20 + col]); \
                ldsm4(al[mi][0], al[mi][1], al[mi][2], al[mi][3], &Alb[row * 20 + col]); \
            }                                                                     \
            unsigned bh[4][4], bl[4][4];                                          \
            _Pragma("unroll") for (int jp = 0; jp < 4; jp++) {                    \
                int row = wn * 64 + jp * 16 + b_r;                                \
                int col = kt * 8 + b_c;                                           \
                ldsm4(bh[jp][0], bh[jp][1], bh[jp][2], bh[jp][3], &Whb[row * 20 + col]); \
                ldsm4(bl[jp][0], bl[jp][1], bl[jp][2], bl[jp][3], &Wlb[row * 20 + col]); \
            }                                                                     \
            _Pragma("unroll") for (int mi = 0; mi < 2; mi++)                      \
                _Pragma("unroll") for (int jp = 0; jp < 4; jp++) {                \
                    mma16(acc[mi][jp * 2], ah[mi], bh[jp]);                       \
                    mma16(acc[mi][jp * 2 + 1], ah[mi], bh[jp] + 2);               \
                }                                                                 \
            _Pragma("unroll") for (int mi = 0; mi < 2; mi++)                      \
                _Pragma("unroll") for (int jp = 0; jp < 4; jp++) {                \
                    mma16(acc[mi][jp * 2], ah[mi], bl[jp]);                       \
                    mma16(acc[mi][jp * 2 + 1], ah[mi], bl[jp] + 2);               \
                }                                                                 \
            _Pragma("unroll") for (int mi = 0; mi < 2; mi++)                      \
                _Pragma("unroll") for (int jp = 0; jp < 4; jp++) {                \
                    mma16(acc[mi][jp * 2], al[mi], bh[jp]);                       \
                    mma16(acc[mi][jp * 2 + 1], al[mi], bh[jp] + 2);               \
                }                                                                 \
        }                                                                         \
        __syncthreads();                                                          \
    }

#define G_LOAD(Ah, Al, Wh, Wl, stage, ku0)                                        \
    do {                                                                          \
        cp16(&Ahs[(stage) * 2560 + lrow * 20 + lch], Ah + (size_t)(m0 + lrow) * KU + (ku0) + lch);          \
        cp16(&Ahs[(stage) * 2560 + (lrow + 64) * 20 + lch], Ah + (size_t)(m0 + lrow + 64) * KU + (ku0) + lch); \
        cp16(&Als[(stage) * 2560 + lrow * 20 + lch], Al + (size_t)(m0 + lrow) * KU + (ku0) + lch);          \
        cp16(&Als[(stage) * 2560 + (lrow + 64) * 20 + lch], Al + (size_t)(m0 + lrow + 64) * KU + (ku0) + lch); \
        cp16(&Whs[(stage) * 2560 + lrow * 20 + lch], Wh + (size_t)(n0 + lrow) * KU + (ku0) + lch);          \
        cp16(&Whs[(stage) * 2560 + (lrow + 64) * 20 + lch], Wh + (size_t)(n0 + lrow + 64) * KU + (ku0) + lch); \
        cp16(&Wls[(stage) * 2560 + lrow * 20 + lch], Wl + (size_t)(n0 + lrow) * KU + (ku0) + lch);          \
        cp16(&Wls[(stage) * 2560 + (lrow + 64) * 20 + lch], Wl + (size_t)(n0 + lrow + 64) * KU + (ku0) + lch); \
        CP_COMMIT();                                                              \
    } while (0)

// ---------------- generic GEMM (proj): fp32 + bias epilogue --------------------
__global__ __launch_bounds__(256, 2) void gemm3b(const unsigned* __restrict__ Ah,
                                                 const unsigned* __restrict__ Al,
                                                 const unsigned* __restrict__ Wh,
                                                 const unsigned* __restrict__ Wl,
                                                 const float* __restrict__ bias,
                                                 float* __restrict__ C,
                                                 int M, int Nn, int K) {
    GEMM_MAIN(Ah, Al, Wh, Wl, K)
#pragma unroll
    for (int j = 0; j < 8; j++) {
        int col = n0 + wn * 64 + j * 8 + tg * 2;
        float2 bv = *(const float2*)(bias + col);
#pragma unroll
        for (int mi = 0; mi < 2; mi++) {
            int row = m0 + wm * 32 + mi * 16 + g;
            float2 o0 = make_float2(acc[mi][j][0] + bv.x, acc[mi][j][1] + bv.y);
            float2 o1 = make_float2(acc[mi][j][2] + bv.x, acc[mi][j][3] + bv.y);
            *(float2*)(C + (size_t)row * Nn + col) = o0;
            *(float2*)(C + (size_t)(row + 8) * Nn + col) = o1;
        }
    }
}

// ---------------- qkv GEMM with fused reorg epilogue ---------------------------
__global__ __launch_bounds__(256, 2) void gemm_qkv(const unsigned* __restrict__ Ah,
                                                   const unsigned* __restrict__ Al,
                                                   const unsigned* __restrict__ Wh,
                                                   const unsigned* __restrict__ Wl,
                                                   const float* __restrict__ bias,
                                                   const float* __restrict__ qe,
                                                   const float* __restrict__ temp,
                                                   int K) {
    GEMM_MAIN(Ah, Al, Wh, Wl, K)
    int bx = blockIdx.x;
    int type = bx >> 2;                      // 0=q, 1=k, 2=v
    int h0 = (bx & 3) * 4 + wn * 2;
#pragma unroll
    for (int j = 0; j < 8; j++) {
        int col = n0 + wn * 64 + j * 8 + tg * 2;
        float2 bv = *(const float2*)(bias + col);
#pragma unroll
        for (int mi = 0; mi < 2; mi++) {
            acc[mi][j][0] += bv.x; acc[mi][j][1] += bv.y;
            acc[mi][j][2] += bv.x; acc[mi][j][3] += bv.y;
        }
    }
    if (type < 2) {
#pragma unroll
        for (int mi = 0; mi < 2; mi++) {
#pragma unroll
            for (int half = 0; half < 2; half++) {
                float s0 = 0.0f, s1 = 0.0f;
#pragma unroll
                for (int jj = 0; jj < 4; jj++) {
                    int j = half * 4 + jj;
                    s0 += acc[mi][j][0] * acc[mi][j][0] + acc[mi][j][1] * acc[mi][j][1];
                    s1 += acc[mi][j][2] * acc[mi][j][2] + acc[mi][j][3] * acc[mi][j][3];
                }
                s0 += __shfl_xor_sync(0xffffffffu, s0, 1);
                s0 += __shfl_xor_sync(0xffffffffu, s0, 2);
                s1 += __shfl_xor_sync(0xffffffffu, s1, 1);
                s1 += __shfl_xor_sync(0xffffffffu, s1, 2);
                float inv0 = 1.0f / fmaxf(sqrtf(s0), 1e-12f);
                float inv1 = 1.0f / fmaxf(sqrtf(s1), 1e-12f);
#pragma unroll
                for (int jj = 0; jj < 4; jj++) {
                    int j = half * 4 + jj;
                    acc[mi][j][0] *= inv0; acc[mi][j][1] *= inv0;
                    acc[mi][j][2] *= inv1; acc[mi][j][3] *= inv1;
                }
            }
        }
        if (type == 0) {
            float t0 = temp[h0], t1 = temp[h0 + 1];
            float sc0 = ((t0 > 20.0f) ? t0 : log1pf(expf(t0))) * SEQ_SCALE;
            float sc1 = ((t1 > 20.0f) ? t1 : log1pf(expf(t1))) * SEQ_SCALE;
#pragma unroll
            for (int j = 0; j < 8; j++) {
                int h = h0 + (j >> 2);
                float sc = (j >> 2) ? sc1 : sc0;
                int d = (j & 3) * 8 + tg * 2;
                float2 q2 = *(const float2*)(qe + h * HD + d);
#pragma unroll
                for (int mi = 0; mi < 2; mi++) {
                    acc[mi][j][0] = (acc[mi][j][0] + q2.x) * sc;
                    acc[mi][j][1] = (acc[mi][j][1] + q2.y) * sc;
                    acc[mi][j][2] = (acc[mi][j][2] + q2.x) * sc;
                    acc[mi][j][3] = (acc[mi][j][3] + q2.y) * sc;
                }
            }
        }
        unsigned* Dh = (type == 0) ? g_qh : g_kh;
        unsigned* Dl = (type == 0) ? g_ql : g_kl;
#pragma unroll
        for (int j = 0; j < 8; j++) {
            int h = h0 + (j >> 2);
            int pc = (j & 3) * 4 + tg;
#pragma unroll
            for (int mi = 0; mi < 2; mi++) {
                int row = m0 + wm * 32 + mi * 16 + g;
                int bb = row >> 10, nn = row & 1023;
                size_t base = ((size_t)(bb * NH + h) * NTOK + nn) * 16 + pc;
                unsigned hw, lw;
                bf16_split2(acc[mi][j][0], acc[mi][j][1], hw, lw);
                Dh[base] = hw; Dl[base] = lw;
                int row2 = row + 8;
                int bb2 = row2 >> 10, nn2 = row2 & 1023;
                size_t base2 = ((size_t)(bb2 * NH + h) * NTOK + nn2) * 16 + pc;
                bf16_split2(acc[mi][j][2], acc[mi][j][3], hw, lw);
                Dh[base2] = hw; Dl[base2] = lw;
            }
        }
    } else {
#pragma unroll
        for (int j = 0; j < 8; j++) {
            int h = h0 + (j >> 2);
            int pc = (j & 3) * 4 + tg;
#pragma unroll
            for (int mi = 0; mi < 2; mi++) {
                int row = m0 + wm * 32 + mi * 16 + g;
                int bb = row >> 10, nn = row & 1023;
                g_vh[((size_t)(bb * NH + h) * NTOK + nn) * 16 + pc] =
                    h2pack(acc[mi][j][0], acc[mi][j][1]);
                int row2 = row + 8;
                int bb2 = row2 >> 10, nn2 = row2 & 1023;
                g_vh[((size_t)(bb2 * NH + h) * NTOK + nn2) * 16 + pc] =
                    h2pack(acc[mi][j][2], acc[mi][j][3]);
            }
        }
    }
}

// ---------------- attention: online softmax + register-P fp16 PV ---------------
// term-major QK MMA ordering (reuse distance 8 per accumulator)
#define ATTN_SMEM ((3 * 2560 + 9216) * 4)
__global__ __launch_bounds__(256, 2) void attn15_kernel() {
    extern __shared__ unsigned smu[];
    unsigned* Khs = smu;                     // [2][1280]
    unsigned* Kls = smu + 2560;
    unsigned* Vhs = smu + 5120;              // [2][1280]
    __half*  BBh = (__half*)(smu + 7680);    // [2][128*72]

    int b = blockIdx.x, qt = blockIdx.y, h = blockIdx.z;
    int tid = threadIdx.x;
    int w = tid >> 5, lane = tid & 31;
    int g = lane >> 2, tg = lane & 3;

    size_t bh16 = (size_t)(b * NH + h) * NTOK * (HD / 2);
    const unsigned* qhb = g_qh + bh16 + (size_t)qt * 128 * (HD / 2);
    const unsigned* qlb = g_ql + bh16 + (size_t)qt * 128 * (HD / 2);
    const unsigned* khb = g_kh + bh16;
    const unsigned* klb = g_kl + bh16;
    const unsigned* vhb = g_vh + bh16;
    const __half* bbh = g_biash + ((size_t)h * NTOK + qt * 128) * NTOK;

    int krow = tid >> 2, kch = (tid & 3) * 4;
    int brow = tid >> 3, bch = (tid & 7) * 8;
    int b_r = (lane >> 4) * 8 + (lane & 7), b_c = ((lane >> 3) & 1) * 4;
    int v_r = ((lane >> 3) & 1) * 8 + (lane & 7), v_c = (lane >> 4) * 4;
#define KVB_LOAD(stage, mt_)                                                      \
    do {                                                                          \
        cp16(&Khs[(stage) * 1280 + krow * 20 + kch], khb + (size_t)((mt_) * 64 + krow) * 16 + kch); \
        cp16(&Kls[(stage) * 1280 + krow * 20 + kch], klb + (size_t)((mt_) * 64 + krow) * 16 + kch); \
        cp16(&Vhs[(stage) * 1280 + krow * 20 + kch], vhb + (size_t)((mt_) * 64 + krow) * 16 + kch); \
        _Pragma("unroll")                                                         \
        for (int p = 0; p < 4; p++) {                                             \
            int row = brow + p * 32;                                              \
            cp16(&BBh[(stage) * 9216 + row * 72 + bch],                           \
                 bbh + (size_t)row * NTOK + (mt_) * 64 + bch);                    \
        }                                                                         \
        CP_COMMIT();                                                              \
    } while (0)

    KVB_LOAD(0, 0);

    unsigned Qh[2][4], Ql[2][4];
    int r = w * 16 + g;
#pragma unroll
    for (int kt = 0; kt < 2; kt++) {
        int c = kt * 8 + tg;
        Qh[kt][0] = qhb[r * 16 + c];           Ql[kt][0] = qlb[r * 16 + c];
        Qh[kt][1] = qhb[(r + 8) * 16 + c];     Ql[kt][1] = qlb[(r + 8) * 16 + c];
        Qh[kt][2] = qhb[r * 16 + c + 4];       Ql[kt][2] = qlb[r * 16 + c + 4];
        Qh[kt][3] = qhb[(r + 8) * 16 + c + 4]; Ql[kt][3] = qlb[(r + 8) * 16 + c + 4];
    }

    float m0 = -INFINITY, m1 = -INFINITY, l0 = 0.0f, l1 = 0.0f;
    float O[4][4];
#pragma unroll
    for (int j = 0; j < 4; j++)
#pragma unroll
        for (int c = 0; c < 4; c++) O[j][c] = 0.0f;

    for (int mt = 0; mt < 16; mt++) {
        int s = mt & 1;
        CP_WAIT(0);
        __syncthreads();   // tile mt visible; all warps done reading stage s^1
        if (mt + 1 < 16) KVB_LOAD(s ^ 1, mt + 1);

        float S[8][4];
#pragma unroll
        for (int j = 0; j < 8; j++)
#pragma unroll
            for (int c = 0; c < 4; c++) S[j][c] = 0.0f;
        const unsigned* Khb = Khs + s * 1280;
        const unsigned* Klb = Kls + s * 1280;
#pragma unroll
        for (int kt = 0; kt < 2; kt++) {
            unsigned bh2[4][4], bl2[4][4];
#pragma unroll
            for (int jp = 0; jp < 4; jp++) {
                int row = jp * 16 + b_r;
                int col = kt * 8 + b_c;
                ldsm4(bh2[jp][0], bh2[jp][1], bh2[jp][2], bh2[jp][3], &Khb[row * 20 + col]);
                ldsm4(bl2[jp][0], bl2[jp][1], bl2[jp][2], bl2[jp][3], &Klb[row * 20 + col]);
            }
#pragma unroll
            for (int jp = 0; jp < 4; jp++) {
                mma16(S[jp * 2], Qh[kt], bh2[jp]);
                mma16(S[jp * 2 + 1], Qh[kt], bh2[jp] + 2);
            }
#pragma unroll
            for (int jp = 0; jp < 4; jp++) {
                mma16(S[jp * 2], Qh[kt], bl2[jp]);
                mma16(S[jp * 2 + 1], Qh[kt], bl2[jp] + 2);
            }
#pragma unroll
            for (int jp = 0; jp < 4; jp++) {
                mma16(S[jp * 2], Ql[kt], bh2[jp]);
                mma16(S[jp * 2 + 1], Ql[kt], bh2[jp] + 2);
            }
        }
        const __half* Bb = BBh + s * 9216;
#pragma unroll
        for (int j = 0; j < 8; j++) {
            float2 b0 = __half22float2(*(const __half2*)(Bb + r * 72 + j * 8 + tg * 2));
            float2 b1 = __half22float2(*(const __half2*)(Bb + (r + 8) * 72 + j * 8 + tg * 2));
            S[j][0] += b0.x; S[j][1] += b0.y;
            S[j][2] += b1.x; S[j][3] += b1.y;
        }
        float mx0 = -INFINITY, mx1 = -INFINITY;
#pragma unroll
        for (int j = 0; j < 8; j++) {
            mx0 = fmaxf(mx0, fmaxf(S[j][0], S[j][1]));
            mx1 = fmaxf(mx1, fmaxf(S[j][2], S[j][3]));
        }
        mx0 = fmaxf(mx0, __shfl_xor_sync(0xffffffffu, mx0, 1));
        mx0 = fmaxf(mx0, __shfl_xor_sync(0xffffffffu, mx0, 2));
        mx1 = fmaxf(mx1, __shfl_xor_sync(0xffffffffu, mx1, 1));
        mx1 = fmaxf(mx1, __shfl_xor_sync(0xffffffffu, mx1, 2));
        float mn0 = fmaxf(m0, mx0), mn1 = fmaxf(m1, mx1);
        float alpha0 = __expf(m0 - mn0), alpha1 = __expf(m1 - mn1);
        m0 = mn0; m1 = mn1;
        float rs0 = 0.0f, rs1 = 0.0f;
#pragma unroll
        for (int j = 0; j < 8; j++) {
            S[j][0] = __expf(S[j][0] - mn0);
            S[j][1] = __expf(S[j][1] - mn0);
            S[j][2] = __expf(S[j][2] - mn1);
            S[j][3] = __expf(S[j][3] - mn1);
            rs0 += S[j][0] + S[j][1];
            rs1 += S[j][2] + S[j][3];
        }
        rs0 += __shfl_xor_sync(0xffffffffu, rs0, 1);
        rs0 += __shfl_xor_sync(0xffffffffu, rs0, 2);
        rs1 += __shfl_xor_sync(0xffffffffu, rs1, 1);
        rs1 += __shfl_xor_sync(0xffffffffu, rs1, 2);
        l0 = l0 * alpha0 + rs0;
        l1 = l1 * alpha1 + rs1;
#pragma unroll
        for (int j = 0; j < 4; j++) {
            O[j][0] *= alpha0; O[j][1] *= alpha0;
            O[j][2] *= alpha1; O[j][3] *= alpha1;
        }
        unsigned Pa[4][4];
#pragma unroll
        for (int kt = 0; kt < 4; kt++) {
            Pa[kt][0] = h2pack(S[2 * kt][0], S[2 * kt][1]);
            Pa[kt][1] = h2pack(S[2 * kt][2], S[2 * kt][3]);
            Pa[kt][2] = h2pack(S[2 * kt + 1][0], S[2 * kt + 1][1]);
            Pa[kt][3] = h2pack(S[2 * kt + 1][2], S[2 * kt + 1][3]);
        }
        const unsigned* Vb = Vhs + s * 1280;
#pragma unroll
        for (int kt = 0; kt < 4; kt++) {
            int row = kt * 16 + v_r;
            unsigned bv[8];
            ldsm4t(bv[0], bv[1], bv[2], bv[3], &Vb[row * 20 + v_c]);
            ldsm4t(bv[4], bv[5], bv[6], bv[7], &Vb[row * 20 + 8 + v_c]);
            mma16h(O[0], Pa[kt], bv + 0);
            mma16h(O[1], Pa[kt], bv + 2);
            mma16h(O[2], Pa[kt], bv + 4);
            mma16h(O[3], Pa[kt], bv + 6);
        }
    }
    float inv0 = 1.0f / l0, inv1 = 1.0f / l1;
    int q0r = qt * 128 + w * 16 + g;
    size_t row0 = (size_t)b * NTOK + q0r;
    int colbase = h * 16;
#pragma unroll
    for (int j = 0; j < 4; j++) {
        unsigned hw, lw;
        bf16_split2(O[j][0] * inv0, O[j][1] * inv0, hw, lw);
        g_oh[row0 * 256 + colbase + j * 4 + tg] = hw;
        g_ol[row0 * 256 + colbase + j * 4 + tg] = lw;
        bf16_split2(O[j][2] * inv1, O[j][3] * inv1, hw, lw);
        g_oh[(row0 + 8) * 256 + colbase + j * 4 + tg] = hw;
        g_ol[(row0 + 8) * 256 + colbase + j * 4 + tg] = lw;
    }
}

// ---------------- launcher: fork-join streams under graph capture --------------
extern "C" void kernel_launch(void* const* d_in, const int* in_sizes, int n_in,
                              void* d_out, int out_size) {
    const float* x      = (const float*)d_in[0];
    const int*   rpi    = (const int*)d_in[3];
    const float* table  = (const float*)d_in[4];
    const float* qkv_w  = (const float*)d_in[5];
    const float* qkv_b  = (const float*)d_in[6];
    const float* proj_w = (const float*)d_in[7];
    const float* proj_b = (const float*)d_in[8];
    const float* temp   = (const float*)d_in[9];
    const float* qe     = (const float*)d_in[10];
    const float* fc1w   = (const float*)d_in[11];
    const float* fc1b   = (const float*)d_in[12];
    const float* fc2w   = (const float*)d_in[13];
    const float* fc2b   = (const float*)d_in[14];
    float* out = (float*)d_out;

    unsigned* p_wh; cudaGetSymbolAddress((void**)&p_wh, g_wh);
    unsigned* p_wl; cudaGetSymbolAddress((void**)&p_wl, g_wl);
    unsigned* p_xh; cudaGetSymbolAddress((void**)&p_xh, g_xh);
    unsigned* p_xl; cudaGetSymbolAddress((void**)&p_xl, g_xl);
    unsigned* p_oh; cudaGetSymbolAddress((void**)&p_oh, g_oh);
    unsigned* p_ol; cudaGetSymbolAddress((void**)&p_ol, g_ol);

    static int attr_set = 0;
    static cudaStream_t s2;
    static cudaEvent_t e_fork, e_join;
    if (!attr_set) {
        cudaFuncSetAttribute(attn15_kernel, cudaFuncAttributeMaxDynamicSharedMemorySize,
                             ATTN_SMEM);
        cudaFuncSetAttribute(gemm3b, cudaFuncAttributeMaxDynamicSharedMemorySize,
                             GEMM_SMEM);
        cudaFuncSetAttribute(gemm_qkv, cudaFuncAttributeMaxDynamicSharedMemorySize,
                             GEMM_SMEM);
        cudaStreamCreateWithFlags(&s2, cudaStreamNonBlocking);
        cudaEventCreateWithFlags(&e_fork, cudaEventDisableTiming);
        cudaEventCreateWithFlags(&e_join, cudaEventDisableTiming);
        attr_set = 1;
    }

    // fork: cpb -> bias on side stream (independent of main chain)
    cudaEventRecord(e_fork, 0);
    cudaStreamWaitEvent(s2, e_fork, 0);
    cpb_kernel<<<TABLE_SZ, 512, 0, s2>>>(table, fc1w, fc1b, fc2w, fc2b);
    bias_kernel<<<NTOK, 256, 0, s2>>>(rpi);
    cudaEventRecord(e_join, s2);

    // main chain: split -> fused qkv gemm (writes q/k/v attention-layout directly)
    split_kernel<<<(NW2 + NX2) / 256, 256>>>(qkv_w, proj_w, x);
    {
        dim3 grid(3 * DIMC / 128, BATCH * NTOK / 128);
        gemm_qkv<<<grid, 256, GEMM_SMEM>>>(p_xh, p_xl, p_wh, p_wl, qkv_b,
                                           qe, temp, DIMC);
    }

    // join: attention needs bias
    cudaStreamWaitEvent(0, e_join, 0);
    {
        dim3 grid(BATCH, NTOK / 128, NH);
        attn15_kernel<<<grid, 256, ATTN_SMEM>>>();
    }
    {
        dim3 grid(DIMC / 128, BATCH * NTOK / 128);
        gemm3b<<<grid, 256, GEMM_SMEM>>>(p_oh, p_ol, p_wh + 3 * DIMC * DIMC / 2,
                                         p_wl + 3 * DIMC * DIMC / 2, proj_b, out,
                                         BATCH * NTOK, DIMC, DIMC);
    }
}